// round 11
// baseline (speedup 1.0000x reference)
#include <cuda_runtime.h>
#include <cuda_bf16.h>
#include <cuda_fp16.h>
#include <cstdint>

#define N_NODES 100000
#define N_EDGES 1600000
#define IN_DIM  256
#define OUT_DIM 64
#define NEG_SLOPE 0.01f

#define SCAN_B 512
#define SCAN_NB 196   // 196*512 = 100352 >= N_NODES

#define NGB 782                         // gemm blocks (ceil(100000/128))
#define NCB ((N_EDGES + 1023) / 1024)   // convert blocks, 4 edges/thread

// SMEM map for fat kernel: double-buffered bf16 hi/lo tiles (SW128 swizzle)
#define B_AHI 0
#define B_ALO 16384
#define B_BHI 32768
#define B_BLO 40960
#define BUF_SZ 49152
#define OFF_ATT 98304
#define OFF_SS0 98816
#define OFF_SS1 99328
#define SMEM_TC_TOTAL 99840   // 2 CTAs/SM

// ---------------- scratch (device globals; no allocations allowed) ----------
__device__ __half  g_zh[N_NODES * OUT_DIM];   // z in fp16 (L2-resident, 12.8MB)
__device__ float   g_ssrc[N_NODES];
__device__ float   g_sdst[N_NODES];
__device__ int2    g_sd[N_EDGES];
__device__ float2  g_edge[N_EDGES];     // (ex, src) in CSR order
__device__ int     g_cnt[N_NODES];
__device__ int2    g_offcnt[N_NODES];   // (offset, degree) packed: one LDG.64
__device__ int     g_cur[N_NODES];
__device__ float   g_maxs[2];
__device__ unsigned long long g_scanstate[SCAN_NB];  // (value<<2)|flag

// ---------------- helpers ------------------------------------------------------
__device__ __forceinline__ uint32_t smem_to_u32(const void* p) {
    uint32_t a;
    asm("{ .reg .u64 t; cvta.to.shared.u64 t, %1; cvt.u32.u64 %0, t; }"
        : "=r"(a) : "l"(p));
    return a;
}
__device__ __forceinline__ uint32_t swzoff(int row, int colb) {
    uint32_t b = (uint32_t)(row * 128 + colb);
    return b ^ ((b >> 3) & 0x70);
}
__device__ __forceinline__ uint32_t pack_bf16(float a, float b) {
    uint32_t r;
    asm("{ .reg .b16 l, h;\n\t"
        "cvt.rn.bf16.f32 l, %1;\n\t"
        "cvt.rn.bf16.f32 h, %2;\n\t"
        "mov.b32 %0, {l, h}; }" : "=r"(r) : "f"(a), "f"(b));
    return r;
}
__device__ __forceinline__ float bf16lo_f(uint32_t v) { return __uint_as_float(v << 16); }
__device__ __forceinline__ float bf16hi_f(uint32_t v) { return __uint_as_float(v & 0xffff0000u); }

__device__ __forceinline__ void cvt_granule(const float4& p, const float4& q,
                                            uint4& hi, uint4& lo) {
    hi.x = pack_bf16(p.x, p.y);
    hi.y = pack_bf16(p.z, p.w);
    hi.z = pack_bf16(q.x, q.y);
    hi.w = pack_bf16(q.z, q.w);
    lo.x = pack_bf16(p.x - bf16lo_f(hi.x), p.y - bf16hi_f(hi.x));
    lo.y = pack_bf16(p.z - bf16lo_f(hi.y), p.w - bf16hi_f(hi.y));
    lo.z = pack_bf16(q.x - bf16lo_f(hi.z), q.y - bf16hi_f(hi.z));
    lo.w = pack_bf16(q.z - bf16lo_f(hi.w), q.w - bf16hi_f(hi.w));
}
__device__ __forceinline__ uint4 ldsm4(uint32_t addr) {
    uint4 r;
    asm volatile("ldmatrix.sync.aligned.m8n8.x4.shared.b16 {%0,%1,%2,%3}, [%4];"
        : "=r"(r.x), "=r"(r.y), "=r"(r.z), "=r"(r.w) : "r"(addr));
    return r;
}
__device__ __forceinline__ void mma_bf16(float* d, const uint4& A, uint32_t b0, uint32_t b1) {
    asm volatile("mma.sync.aligned.m16n8k16.row.col.f32.bf16.bf16.f32 "
        "{%0,%1,%2,%3}, {%4,%5,%6,%7}, {%8,%9}, {%0,%1,%2,%3};"
        : "+f"(d[0]), "+f"(d[1]), "+f"(d[2]), "+f"(d[3])
        : "r"(A.x), "r"(A.y), "r"(A.z), "r"(A.w), "r"(b0), "r"(b1));
}
__device__ __forceinline__ void atomicMaxFloat(float* addr, float v) {
    if (v >= 0.0f) atomicMax((int*)addr, __float_as_int(v));
    else           atomicMin((unsigned int*)addr, (unsigned int)__float_as_int(v));
}

// ---- GEMM building blocks ----
__device__ __forceinline__ void ldg_chunk(const float* __restrict__ h,
                                          const float* __restrict__ W,
                                          int r0, int k0, int tid,
                                          float4 fa[4][2], float4 fb[2][2]) {
#pragma unroll
    for (int j = 0; j < 4; j++) {
        int g = tid + j * 256;
        int row = g >> 3, c8 = g & 7;
        int gr = r0 + row;
        if (gr < N_NODES) {
            fa[j][0] = *(const float4*)&h[gr * IN_DIM + k0 + c8 * 8];
            fa[j][1] = *(const float4*)&h[gr * IN_DIM + k0 + c8 * 8 + 4];
        } else {
            fa[j][0] = make_float4(0.f, 0.f, 0.f, 0.f);
            fa[j][1] = make_float4(0.f, 0.f, 0.f, 0.f);
        }
    }
#pragma unroll
    for (int j = 0; j < 2; j++) {
        int g = tid + j * 256;
        int row = g >> 3, c8 = g & 7;
        fb[j][0] = *(const float4*)&W[row * IN_DIM + k0 + c8 * 8];
        fb[j][1] = *(const float4*)&W[row * IN_DIM + k0 + c8 * 8 + 4];
    }
}

__device__ __forceinline__ void cvt_sts(char* smem, int bufbase, int tid,
                                        const float4 fa[4][2], const float4 fb[2][2]) {
#pragma unroll
    for (int j = 0; j < 4; j++) {
        int g = tid + j * 256;
        int row = g >> 3, c8 = g & 7;
        uint4 hi, lo;
        cvt_granule(fa[j][0], fa[j][1], hi, lo);
        uint32_t off = swzoff(row, c8 * 16);
        *(uint4*)(smem + bufbase + B_AHI + off) = hi;
        *(uint4*)(smem + bufbase + B_ALO + off) = lo;
    }
#pragma unroll
    for (int j = 0; j < 2; j++) {
        int g = tid + j * 256;
        int row = g >> 3, c8 = g & 7;
        uint4 hi, lo;
        cvt_granule(fb[j][0], fb[j][1], hi, lo);
        uint32_t off = swzoff(row, c8 * 16);
        *(uint4*)(smem + bufbase + B_BHI + off) = hi;
        *(uint4*)(smem + bufbase + B_BLO + off) = lo;
    }
}

__device__ __forceinline__ void mma_chunk(uint32_t sbuf, int wr, int wc, int lane,
                                          float acc[2][4][4]) {
#pragma unroll
    for (int ks = 0; ks < 4; ks++) {
        uint4 Ah[2], Al[2], Bh[2], Bl[2];
        int arow  = wr * 32 + (lane & 15);
        int acolb = ks * 32 + ((lane >> 4) << 4);
#pragma unroll
        for (int mt = 0; mt < 2; mt++) {
            uint32_t ad = sbuf + B_AHI + swzoff(arow + mt * 16, acolb);
            Ah[mt] = ldsm4(ad);
            Al[mt] = ldsm4(ad + (B_ALO - B_AHI));
        }
        int brow  = wc * 32 + (lane & 7) + ((lane >> 4) << 3);
        int bcolb = ks * 32 + (((lane >> 3) & 1) << 4);
#pragma unroll
        for (int nb = 0; nb < 2; nb++) {
            uint32_t bd = sbuf + B_BHI + swzoff(brow + nb * 16, bcolb);
            Bh[nb] = ldsm4(bd);
            Bl[nb] = ldsm4(bd + (B_BLO - B_BHI));
        }
#pragma unroll
        for (int mt = 0; mt < 2; mt++)
#pragma unroll
            for (int nb = 0; nb < 2; nb++) {
                mma_bf16(acc[mt][nb * 2],     Ah[mt], Bh[nb].x, Bh[nb].y);
                mma_bf16(acc[mt][nb * 2 + 1], Ah[mt], Bh[nb].z, Bh[nb].w);
                mma_bf16(acc[mt][nb * 2],     Al[mt], Bh[nb].x, Bh[nb].y);
                mma_bf16(acc[mt][nb * 2 + 1], Al[mt], Bh[nb].z, Bh[nb].w);
                mma_bf16(acc[mt][nb * 2],     Ah[mt], Bl[nb].x, Bl[nb].y);
                mma_bf16(acc[mt][nb * 2 + 1], Ah[mt], Bl[nb].z, Bl[nb].w);
            }
    }
}

// ---------------- fat kernel: GEMM blocks [0, NGB) + convert blocks [NGB, ...) ---
__global__ __launch_bounds__(256, 2) void k_fat(const float* __restrict__ h,
                                                const float* __restrict__ W,
                                                const float* __restrict__ a_attn,
                                                const void* __restrict__ ei) {
    extern __shared__ char smem[];
    const int bid = blockIdx.x;
    const int tid = threadIdx.x;

    if (bid >= NGB) {
        __shared__ int s_flag;
        if (tid < 32) {
            const long long* p = (const long long*)ei;
            long long v = p[tid];
            int ok = (v >= 0 && v < N_NODES);
            unsigned m = __ballot_sync(0xffffffff, ok);
            if (tid == 0) s_flag = (m == 0xffffffffu);
        }
        __syncthreads();
        int base = (bid - NGB) * 1024 + tid * 4;
        if (base + 3 >= N_EDGES) return;
        int s0, s1, s2, s3, d0, d1, d2, d3;
        if (s_flag) {
            const long long* p = (const long long*)ei;
            longlong2 a = *(const longlong2*)(p + base);
            longlong2 b = *(const longlong2*)(p + base + 2);
            longlong2 c = *(const longlong2*)(p + N_EDGES + base);
            longlong2 d = *(const longlong2*)(p + N_EDGES + base + 2);
            s0 = (int)a.x; s1 = (int)a.y; s2 = (int)b.x; s3 = (int)b.y;
            d0 = (int)c.x; d1 = (int)c.y; d2 = (int)d.x; d3 = (int)d.y;
        } else {
            const int* p = (const int*)ei;
            int4 a = *(const int4*)(p + base);
            int4 c = *(const int4*)(p + N_EDGES + base);
            s0 = a.x; s1 = a.y; s2 = a.z; s3 = a.w;
            d0 = c.x; d1 = c.y; d2 = c.z; d3 = c.w;
        }
        *(int4*)&g_sd[base]     = make_int4(s0, d0, s1, d1);
        *(int4*)&g_sd[base + 2] = make_int4(s2, d2, s3, d3);
        atomicAdd(&g_cnt[d0], 1);
        atomicAdd(&g_cnt[d1], 1);
        atomicAdd(&g_cnt[d2], 1);
        atomicAdd(&g_cnt[d3], 1);
        return;
    }

    // ---------------- GEMM path ----------------
    const uint32_t sb = smem_to_u32(smem);
    const int lane = tid & 31, wid = tid >> 5;
    const int wr = wid & 3, wc = wid >> 2;
    const int r0 = bid * 128;

    float* sS0 = (float*)(smem + OFF_SS0);
    float* sS1 = (float*)(smem + OFF_SS1);
    if (tid < 128) {
        ((float*)(smem + OFF_ATT))[tid] = a_attn[tid];
        sS0[tid] = 0.f;
        sS1[tid] = 0.f;
    }

    float acc[2][4][4];
#pragma unroll
    for (int a = 0; a < 2; a++)
#pragma unroll
        for (int b = 0; b < 4; b++)
#pragma unroll
            for (int c = 0; c < 4; c++) acc[a][b][c] = 0.f;

    float4 fa[4][2], fb[2][2];
    ldg_chunk(h, W, r0, 0, tid, fa, fb);
    cvt_sts(smem, 0, tid, fa, fb);
    __syncthreads();

#pragma unroll
    for (int it = 1; it < 4; it++) {
        ldg_chunk(h, W, r0, it * 64, tid, fa, fb);
        mma_chunk(sb + ((it - 1) & 1) * BUF_SZ, wr, wc, lane, acc);
        cvt_sts(smem, (it & 1) * BUF_SZ, tid, fa, fb);
        __syncthreads();
    }
    mma_chunk(sb + BUF_SZ, wr, wc, lane, acc);

    const float* al = (const float*)(smem + OFF_ATT);
    const float* ar = al + OUT_DIM;
#pragma unroll
    for (int mt = 0; mt < 2; mt++) {
#pragma unroll
        for (int half = 0; half < 2; half++) {
            int lr = wr * 32 + mt * 16 + (lane >> 2) + half * 8;
            int grow = r0 + lr;
            float s0 = 0.f, s1 = 0.f;
#pragma unroll
            for (int nt = 0; nt < 4; nt++) {
                int c = wc * 32 + nt * 8 + (lane & 3) * 2;
                float v0 = acc[mt][nt][half * 2];
                float v1 = acc[mt][nt][half * 2 + 1];
                s0 += v0 * al[c] + v1 * al[c + 1];
                s1 += v0 * ar[c] + v1 * ar[c + 1];
                if (grow < N_NODES)
                    *(__half2*)&g_zh[grow * OUT_DIM + c] = __floats2half2_rn(v0, v1);
            }
            s0 += __shfl_xor_sync(0xffffffff, s0, 1);
            s0 += __shfl_xor_sync(0xffffffff, s0, 2);
            s1 += __shfl_xor_sync(0xffffffff, s1, 1);
            s1 += __shfl_xor_sync(0xffffffff, s1, 2);
            if ((lane & 3) == 0) {
                atomicAdd(&sS0[lr], s0);
                atomicAdd(&sS1[lr], s1);
            }
        }
    }
    __syncthreads();
    if (tid < 128) {
        int grow = r0 + tid;
        float s0 = sS0[tid], s1 = sS1[tid];
        if (grow < N_NODES) {
            g_ssrc[grow] = s0;
            g_sdst[grow] = s1;
        } else {
            s0 = __int_as_float(0xff800000);
            s1 = __int_as_float(0xff800000);
        }
#pragma unroll
        for (int o = 16; o > 0; o >>= 1) {
            s0 = fmaxf(s0, __shfl_xor_sync(0xffffffff, s0, o));
            s1 = fmaxf(s1, __shfl_xor_sync(0xffffffff, s1, o));
        }
        if ((tid & 31) == 0) {
            atomicMaxFloat(&g_maxs[0], s0);
            atomicMaxFloat(&g_maxs[1], s1);
        }
    }
}

// ---------------- single-pass scan with decoupled lookback ----------------------
__global__ void k_scan() {
    __shared__ int wsum[16];
    __shared__ int s_prefix;
    const int b = blockIdx.x, t = threadIdx.x;
    const int lane = t & 31, wid = t >> 5;
    const int i = b * SCAN_B + t;
    int v = (i < N_NODES) ? g_cnt[i] : 0;

    int x = v;
#pragma unroll
    for (int o = 1; o < 32; o <<= 1) {
        int y = __shfl_up_sync(0xffffffff, x, o);
        if (lane >= o) x += y;
    }
    if (lane == 31) wsum[wid] = x;
    __syncthreads();
    if (wid == 0) {
        int s = (lane < 16) ? wsum[lane] : 0;
#pragma unroll
        for (int o = 1; o < 16; o <<= 1) {
            int y = __shfl_up_sync(0xffffffff, s, o);
            if (lane >= o) s += y;
        }
        if (lane < 16) wsum[lane] = s;
    }
    __syncthreads();
    int incl = (wid ? wsum[wid - 1] : 0) + x;

    if (t == SCAN_B - 1) {
        unsigned long long pub = ((unsigned long long)incl << 2) | (b == 0 ? 2u : 1u);
        atomicExch(&g_scanstate[b], pub);
    }

    if (b > 0 && wid == 0) {
        long long run = 0;
        int j = b - 1;
        while (true) {
            int idx = j - lane;
            unsigned long long s;
            if (idx >= 0) {
                do { s = atomicAdd(&g_scanstate[idx], 0ull); } while ((s & 3) == 0);
            } else {
                s = 2ull;
            }
            unsigned mask = __ballot_sync(0xffffffff, (s & 3) == 2);
            long long contrib;
            if (mask) {
                int fl = __ffs(mask) - 1;
                contrib = (lane <= fl) ? (long long)(s >> 2) : 0;
            } else {
                contrib = (long long)(s >> 2);
            }
#pragma unroll
            for (int o = 16; o > 0; o >>= 1)
                contrib += __shfl_xor_sync(0xffffffff, contrib, o);
            run += contrib;
            if (mask) break;
            j -= 32;
        }
        if (lane == 0) s_prefix = (int)run;
    } else if (t == 0) {
        s_prefix = 0;
    }
    __syncthreads();
    int prefix = s_prefix;

    if (b > 0 && t == SCAN_B - 1)
        atomicExch(&g_scanstate[b], (((unsigned long long)(incl + prefix)) << 2) | 2u);

    if (i < N_NODES) {
        int o = prefix + incl - v;
        g_offcnt[i] = make_int2(o, v);   // packed (offset, degree)
        g_cur[i] = o;
    }
}

// 4 edges/thread: ex = exp(lrelu(ssrc[s]+sdst[d]) - M); scatter into CSR slots
__global__ void k_edge_fused() {
    int i = (blockIdx.x * blockDim.x + threadIdx.x) * 4;
    if (i >= N_EDGES) return;
    float M = g_maxs[0] + g_maxs[1];
    int4 a = *(const int4*)&g_sd[i];        // (s0,d0,s1,d1)
    int4 b = *(const int4*)&g_sd[i + 2];    // (s2,d2,s3,d3)
    float ss0 = g_ssrc[a.x], sd0 = g_sdst[a.y];
    float ss1 = g_ssrc[a.z], sd1 = g_sdst[a.w];
    float ss2 = g_ssrc[b.x], sd2 = g_sdst[b.y];
    float ss3 = g_ssrc[b.z], sd3 = g_sdst[b.w];
    float x0 = ss0 + sd0, x1 = ss1 + sd1, x2 = ss2 + sd2, x3 = ss3 + sd3;
    float e0 = x0 > 0.f ? x0 : NEG_SLOPE * x0;
    float e1 = x1 > 0.f ? x1 : NEG_SLOPE * x1;
    float e2 = x2 > 0.f ? x2 : NEG_SLOPE * x2;
    float e3 = x3 > 0.f ? x3 : NEG_SLOPE * x3;
    float ex0 = __expf(e0 - M);
    float ex1 = __expf(e1 - M);
    float ex2 = __expf(e2 - M);
    float ex3 = __expf(e3 - M);
    int p0 = atomicAdd(&g_cur[a.y], 1);
    g_edge[p0] = make_float2(ex0, __int_as_float(a.x));
    int p1 = atomicAdd(&g_cur[a.w], 1);
    g_edge[p1] = make_float2(ex1, __int_as_float(a.z));
    int p2 = atomicAdd(&g_cur[b.y], 1);
    g_edge[p2] = make_float2(ex2, __int_as_float(b.x));
    int p3 = atomicAdd(&g_cur[b.w], 1);
    g_edge[p3] = make_float2(ex3, __int_as_float(b.z));
}

// warp per node; all 32 lanes own disjoint half2 columns, no cross-lane reduce.
// Software-pipelined: next iteration's edge records load while current z-gathers
// are in flight, removing one L2 round-trip from the per-iteration critical path.
__global__ void k_aggregate(float* __restrict__ out) {
    int w    = (blockIdx.x * blockDim.x + threadIdx.x) >> 5;
    int lane = threadIdx.x & 31;
    if (w >= N_NODES) return;
    int2 oc = g_offcnt[w];               // one LDG.64: (offset, degree)
    int base = oc.x, deg = oc.y;
    const __half2* zrow = (const __half2*)g_zh;

    float ax = 0.f, ay = 0.f, wsum = 0.f;
    int j = 0;

#define ACC1(EX, SRCBITS) do {                                    \
        __half2 _z = zrow[__float_as_int(SRCBITS) * 32 + lane];   \
        float2 _f = __half22float2(_z);                            \
        ax += (EX) * _f.x; ay += (EX) * _f.y; wsum += (EX);        \
    } while (0)

    if ((base & 1) && deg > 0) {   // align base for float4 edge loads
        float2 ed = g_edge[base];
        ACC1(ed.x, ed.y);
        j = 1;
    }

    float4 ea, eb, ec, ed4;
    bool have = (j + 8 <= deg);
    if (have) {
        const float4* ep = (const float4*)&g_edge[base + j];
        ea = ep[0]; eb = ep[1]; ec = ep[2]; ed4 = ep[3];
    }
    while (have) {
        // issue current 8 z-gathers
        __half2 z0 = zrow[__float_as_int(ea.y) * 32 + lane];
        __half2 z1 = zrow[__float_as_int(ea.w) * 32 + lane];
        __half2 z2 = zrow[__float_as_int(eb.y) * 32 + lane];
        __half2 z3 = zrow[__float_as_int(eb.w) * 32 + lane];
        __half2 z4 = zrow[__float_as_int(ec.y) * 32 + lane];
        __half2 z5 = zrow[__float_as_int(ec.w) * 32 + lane];
        __half2 z6 = zrow[__float_as_int(ed4.y) * 32 + lane];
        __half2 z7 = zrow[__float_as_int(ed4.w) * 32 + lane];
        // prefetch next 8 edge records while gathers are in flight
        bool nxt = (j + 16 <= deg);
        float4 na, nb, nc, nd;
        if (nxt) {
            const float4* np = (const float4*)&g_edge[base + j + 8];
            na = np[0]; nb = np[1]; nc = np[2]; nd = np[3];
        }
        // consume
        float2 f;
        f = __half22float2(z0); ax += ea.x  * f.x; ay += ea.x  * f.y;
        f = __half22float2(z1); ax += ea.z  * f.x; ay += ea.z  * f.y;
        f = __half22float2(z2); ax += eb.x  * f.x; ay += eb.x  * f.y;
        f = __half22float2(z3); ax += eb.z  * f.x; ay += eb.z  * f.y;
        f = __half22float2(z4); ax += ec.x  * f.x; ay += ec.x  * f.y;
        f = __half22float2(z5); ax += ec.z  * f.x; ay += ec.z  * f.y;
        f = __half22float2(z6); ax += ed4.x * f.x; ay += ed4.x * f.y;
        f = __half22float2(z7); ax += ed4.z * f.x; ay += ed4.z * f.y;
        wsum += (ea.x + ea.z) + (eb.x + eb.z) + (ec.x + ec.z) + (ed4.x + ed4.z);
        j += 8;
        if (nxt) { ea = na; eb = nb; ec = nc; ed4 = nd; }
        have = nxt;
    }
    if (j + 4 <= deg) {
        const float4* ep = (const float4*)&g_edge[base + j];
        float4 pa = ep[0];
        float4 pb = ep[1];
        __half2 z0 = zrow[__float_as_int(pa.y) * 32 + lane];
        __half2 z1 = zrow[__float_as_int(pa.w) * 32 + lane];
        __half2 z2 = zrow[__float_as_int(pb.y) * 32 + lane];
        __half2 z3 = zrow[__float_as_int(pb.w) * 32 + lane];
        float2 f;
        f = __half22float2(z0); ax += pa.x * f.x; ay += pa.x * f.y;
        f = __half22float2(z1); ax += pa.z * f.x; ay += pa.z * f.y;
        f = __half22float2(z2); ax += pb.x * f.x; ay += pb.x * f.y;
        f = __half22float2(z3); ax += pb.z * f.x; ay += pb.z * f.y;
        wsum += (pa.x + pa.z) + (pb.x + pb.z);
        j += 4;
    }
    for (; j < deg; j++) {
        float2 ed = g_edge[base + j];
        ACC1(ed.x, ed.y);
    }
#undef ACC1

    float inv = wsum > 0.f ? 1.f / wsum : 0.f;
    *(float2*)&out[w * OUT_DIM + lane * 2] = make_float2(ax * inv, ay * inv);
}

// ---------------- launch --------------------------------------------------------
extern "C" void kernel_launch(void* const* d_in, const int* in_sizes, int n_in,
                              void* d_out, int out_size) {
    const float* h = (const float*)d_in[0];
    const float* W = (const float*)d_in[1];
    const float* a = (const float*)d_in[2];
    const void*  ei = d_in[3];
    float* out = (float*)d_out;

    cudaFuncSetAttribute(k_fat, cudaFuncAttributeMaxDynamicSharedMemorySize, SMEM_TC_TOTAL);

    void* p_cnt = nullptr;
    void* p_maxs = nullptr;
    void* p_scan = nullptr;
    cudaGetSymbolAddress(&p_cnt, g_cnt);
    cudaGetSymbolAddress(&p_maxs, g_maxs);
    cudaGetSymbolAddress(&p_scan, g_scanstate);
    cudaMemsetAsync(p_cnt, 0, N_NODES * sizeof(int));
    cudaMemsetAsync(p_maxs, 0xFF, 2 * sizeof(float));
    cudaMemsetAsync(p_scan, 0, SCAN_NB * sizeof(unsigned long long));

    k_fat<<<NGB + NCB, 256, SMEM_TC_TOTAL>>>(h, W, a, ei);
    k_scan<<<SCAN_NB, SCAN_B>>>();
    k_edge_fused<<<(N_EDGES / 4 + 255) / 256, 256>>>();
    k_aggregate<<<(N_NODES * 32 + 255) / 256, 256>>>(out);
}

// round 12
// speedup vs baseline: 1.1398x; 1.1398x over previous
#include <cuda_runtime.h>
#include <cuda_bf16.h>
#include <cuda_fp16.h>
#include <cstdint>

#define N_NODES 100000
#define N_EDGES 1600000
#define IN_DIM  256
#define OUT_DIM 64
#define NEG_SLOPE 0.01f

#define SCAN_B 512
#define SCAN_NB 196   // 196*512 = 100352 >= N_NODES

#define NGB 782                         // gemm blocks (ceil(100000/128))
#define NCB ((N_EDGES + 1023) / 1024)   // convert blocks, 4 edges/thread

// SMEM map for fat kernel: double-buffered bf16 hi/lo tiles (SW128 swizzle)
#define B_AHI 0
#define B_ALO 16384
#define B_BHI 32768
#define B_BLO 40960
#define BUF_SZ 49152
#define OFF_ATT 98304
#define OFF_SS0 98816
#define OFF_SS1 99328
#define SMEM_TC_TOTAL 99840   // 2 CTAs/SM

// ---------------- scratch (device globals; no allocations allowed) ----------
__device__ __half  g_zh[N_NODES * OUT_DIM];   // z in fp16 (L2-resident, 12.8MB)
__device__ float   g_ssrc[N_NODES];
__device__ float   g_sdst[N_NODES];
__device__ int2    g_sd[N_EDGES];
__device__ float2  g_edge[N_EDGES];     // (ex, src) in CSR order
__device__ int     g_cnt[N_NODES];
__device__ int2    g_offcnt[N_NODES];   // (offset, degree) packed: one LDG.64
__device__ int     g_cur[N_NODES];
__device__ float   g_maxs[2];
__device__ unsigned long long g_scanstate[SCAN_NB];  // (value<<2)|flag

// ---------------- helpers ------------------------------------------------------
__device__ __forceinline__ uint32_t smem_to_u32(const void* p) {
    uint32_t a;
    asm("{ .reg .u64 t; cvta.to.shared.u64 t, %1; cvt.u32.u64 %0, t; }"
        : "=r"(a) : "l"(p));
    return a;
}
__device__ __forceinline__ uint32_t swzoff(int row, int colb) {
    uint32_t b = (uint32_t)(row * 128 + colb);
    return b ^ ((b >> 3) & 0x70);
}
__device__ __forceinline__ uint32_t pack_bf16(float a, float b) {
    uint32_t r;
    asm("{ .reg .b16 l, h;\n\t"
        "cvt.rn.bf16.f32 l, %1;\n\t"
        "cvt.rn.bf16.f32 h, %2;\n\t"
        "mov.b32 %0, {l, h}; }" : "=r"(r) : "f"(a), "f"(b));
    return r;
}
__device__ __forceinline__ float bf16lo_f(uint32_t v) { return __uint_as_float(v << 16); }
__device__ __forceinline__ float bf16hi_f(uint32_t v) { return __uint_as_float(v & 0xffff0000u); }

__device__ __forceinline__ void cvt_granule(const float4& p, const float4& q,
                                            uint4& hi, uint4& lo) {
    hi.x = pack_bf16(p.x, p.y);
    hi.y = pack_bf16(p.z, p.w);
    hi.z = pack_bf16(q.x, q.y);
    hi.w = pack_bf16(q.z, q.w);
    lo.x = pack_bf16(p.x - bf16lo_f(hi.x), p.y - bf16hi_f(hi.x));
    lo.y = pack_bf16(p.z - bf16lo_f(hi.y), p.w - bf16hi_f(hi.y));
    lo.z = pack_bf16(q.x - bf16lo_f(hi.z), q.y - bf16hi_f(hi.z));
    lo.w = pack_bf16(q.z - bf16lo_f(hi.w), q.w - bf16hi_f(hi.w));
}
__device__ __forceinline__ uint4 ldsm4(uint32_t addr) {
    uint4 r;
    asm volatile("ldmatrix.sync.aligned.m8n8.x4.shared.b16 {%0,%1,%2,%3}, [%4];"
        : "=r"(r.x), "=r"(r.y), "=r"(r.z), "=r"(r.w) : "r"(addr));
    return r;
}
__device__ __forceinline__ void mma_bf16(float* d, const uint4& A, uint32_t b0, uint32_t b1) {
    asm volatile("mma.sync.aligned.m16n8k16.row.col.f32.bf16.bf16.f32 "
        "{%0,%1,%2,%3}, {%4,%5,%6,%7}, {%8,%9}, {%0,%1,%2,%3};"
        : "+f"(d[0]), "+f"(d[1]), "+f"(d[2]), "+f"(d[3])
        : "r"(A.x), "r"(A.y), "r"(A.z), "r"(A.w), "r"(b0), "r"(b1));
}
__device__ __forceinline__ void atomicMaxFloat(float* addr, float v) {
    if (v >= 0.0f) atomicMax((int*)addr, __float_as_int(v));
    else           atomicMin((unsigned int*)addr, (unsigned int)__float_as_int(v));
}

// ---- GEMM building blocks ----
__device__ __forceinline__ void ldg_chunk(const float* __restrict__ h,
                                          const float* __restrict__ W,
                                          int r0, int k0, int tid,
                                          float4 fa[4][2], float4 fb[2][2]) {
#pragma unroll
    for (int j = 0; j < 4; j++) {
        int g = tid + j * 256;
        int row = g >> 3, c8 = g & 7;
        int gr = r0 + row;
        if (gr < N_NODES) {
            fa[j][0] = *(const float4*)&h[gr * IN_DIM + k0 + c8 * 8];
            fa[j][1] = *(const float4*)&h[gr * IN_DIM + k0 + c8 * 8 + 4];
        } else {
            fa[j][0] = make_float4(0.f, 0.f, 0.f, 0.f);
            fa[j][1] = make_float4(0.f, 0.f, 0.f, 0.f);
        }
    }
#pragma unroll
    for (int j = 0; j < 2; j++) {
        int g = tid + j * 256;
        int row = g >> 3, c8 = g & 7;
        fb[j][0] = *(const float4*)&W[row * IN_DIM + k0 + c8 * 8];
        fb[j][1] = *(const float4*)&W[row * IN_DIM + k0 + c8 * 8 + 4];
    }
}

__device__ __forceinline__ void cvt_sts(char* smem, int bufbase, int tid,
                                        const float4 fa[4][2], const float4 fb[2][2]) {
#pragma unroll
    for (int j = 0; j < 4; j++) {
        int g = tid + j * 256;
        int row = g >> 3, c8 = g & 7;
        uint4 hi, lo;
        cvt_granule(fa[j][0], fa[j][1], hi, lo);
        uint32_t off = swzoff(row, c8 * 16);
        *(uint4*)(smem + bufbase + B_AHI + off) = hi;
        *(uint4*)(smem + bufbase + B_ALO + off) = lo;
    }
#pragma unroll
    for (int j = 0; j < 2; j++) {
        int g = tid + j * 256;
        int row = g >> 3, c8 = g & 7;
        uint4 hi, lo;
        cvt_granule(fb[j][0], fb[j][1], hi, lo);
        uint32_t off = swzoff(row, c8 * 16);
        *(uint4*)(smem + bufbase + B_BHI + off) = hi;
        *(uint4*)(smem + bufbase + B_BLO + off) = lo;
    }
}

__device__ __forceinline__ void mma_chunk(uint32_t sbuf, int wr, int wc, int lane,
                                          float acc[2][4][4]) {
#pragma unroll
    for (int ks = 0; ks < 4; ks++) {
        uint4 Ah[2], Al[2], Bh[2], Bl[2];
        int arow  = wr * 32 + (lane & 15);
        int acolb = ks * 32 + ((lane >> 4) << 4);
#pragma unroll
        for (int mt = 0; mt < 2; mt++) {
            uint32_t ad = sbuf + B_AHI + swzoff(arow + mt * 16, acolb);
            Ah[mt] = ldsm4(ad);
            Al[mt] = ldsm4(ad + (B_ALO - B_AHI));
        }
        int brow  = wc * 32 + (lane & 7) + ((lane >> 4) << 3);
        int bcolb = ks * 32 + (((lane >> 3) & 1) << 4);
#pragma unroll
        for (int nb = 0; nb < 2; nb++) {
            uint32_t bd = sbuf + B_BHI + swzoff(brow + nb * 16, bcolb);
            Bh[nb] = ldsm4(bd);
            Bl[nb] = ldsm4(bd + (B_BLO - B_BHI));
        }
#pragma unroll
        for (int mt = 0; mt < 2; mt++)
#pragma unroll
            for (int nb = 0; nb < 2; nb++) {
                mma_bf16(acc[mt][nb * 2],     Ah[mt], Bh[nb].x, Bh[nb].y);
                mma_bf16(acc[mt][nb * 2 + 1], Ah[mt], Bh[nb].z, Bh[nb].w);
                mma_bf16(acc[mt][nb * 2],     Al[mt], Bh[nb].x, Bh[nb].y);
                mma_bf16(acc[mt][nb * 2 + 1], Al[mt], Bh[nb].z, Bh[nb].w);
                mma_bf16(acc[mt][nb * 2],     Ah[mt], Bl[nb].x, Bl[nb].y);
                mma_bf16(acc[mt][nb * 2 + 1], Ah[mt], Bl[nb].z, Bl[nb].w);
            }
    }
}

// ---------------- fat kernel: GEMM blocks [0, NGB) + convert blocks [NGB, ...) ---
__global__ __launch_bounds__(256, 2) void k_fat(const float* __restrict__ h,
                                                const float* __restrict__ W,
                                                const float* __restrict__ a_attn,
                                                const void* __restrict__ ei) {
    extern __shared__ char smem[];
    const int bid = blockIdx.x;
    const int tid = threadIdx.x;

    if (bid >= NGB) {
        __shared__ int s_flag;
        if (tid < 32) {
            const long long* p = (const long long*)ei;
            long long v = p[tid];
            int ok = (v >= 0 && v < N_NODES);
            unsigned m = __ballot_sync(0xffffffff, ok);
            if (tid == 0) s_flag = (m == 0xffffffffu);
        }
        __syncthreads();
        int base = (bid - NGB) * 1024 + tid * 4;
        if (base + 3 >= N_EDGES) return;
        int s0, s1, s2, s3, d0, d1, d2, d3;
        if (s_flag) {
            const long long* p = (const long long*)ei;
            longlong2 a = *(const longlong2*)(p + base);
            longlong2 b = *(const longlong2*)(p + base + 2);
            longlong2 c = *(const longlong2*)(p + N_EDGES + base);
            longlong2 d = *(const longlong2*)(p + N_EDGES + base + 2);
            s0 = (int)a.x; s1 = (int)a.y; s2 = (int)b.x; s3 = (int)b.y;
            d0 = (int)c.x; d1 = (int)c.y; d2 = (int)d.x; d3 = (int)d.y;
        } else {
            const int* p = (const int*)ei;
            int4 a = *(const int4*)(p + base);
            int4 c = *(const int4*)(p + N_EDGES + base);
            s0 = a.x; s1 = a.y; s2 = a.z; s3 = a.w;
            d0 = c.x; d1 = c.y; d2 = c.z; d3 = c.w;
        }
        *(int4*)&g_sd[base]     = make_int4(s0, d0, s1, d1);
        *(int4*)&g_sd[base + 2] = make_int4(s2, d2, s3, d3);
        atomicAdd(&g_cnt[d0], 1);
        atomicAdd(&g_cnt[d1], 1);
        atomicAdd(&g_cnt[d2], 1);
        atomicAdd(&g_cnt[d3], 1);
        return;
    }

    // ---------------- GEMM path ----------------
    const uint32_t sb = smem_to_u32(smem);
    const int lane = tid & 31, wid = tid >> 5;
    const int wr = wid & 3, wc = wid >> 2;
    const int r0 = bid * 128;

    float* sS0 = (float*)(smem + OFF_SS0);
    float* sS1 = (float*)(smem + OFF_SS1);
    if (tid < 128) {
        ((float*)(smem + OFF_ATT))[tid] = a_attn[tid];
        sS0[tid] = 0.f;
        sS1[tid] = 0.f;
    }

    float acc[2][4][4];
#pragma unroll
    for (int a = 0; a < 2; a++)
#pragma unroll
        for (int b = 0; b < 4; b++)
#pragma unroll
            for (int c = 0; c < 4; c++) acc[a][b][c] = 0.f;

    float4 fa[4][2], fb[2][2];
    ldg_chunk(h, W, r0, 0, tid, fa, fb);
    cvt_sts(smem, 0, tid, fa, fb);
    __syncthreads();

#pragma unroll
    for (int it = 1; it < 4; it++) {
        ldg_chunk(h, W, r0, it * 64, tid, fa, fb);
        mma_chunk(sb + ((it - 1) & 1) * BUF_SZ, wr, wc, lane, acc);
        cvt_sts(smem, (it & 1) * BUF_SZ, tid, fa, fb);
        __syncthreads();
    }
    mma_chunk(sb + BUF_SZ, wr, wc, lane, acc);

    const float* al = (const float*)(smem + OFF_ATT);
    const float* ar = al + OUT_DIM;
#pragma unroll
    for (int mt = 0; mt < 2; mt++) {
#pragma unroll
        for (int half = 0; half < 2; half++) {
            int lr = wr * 32 + mt * 16 + (lane >> 2) + half * 8;
            int grow = r0 + lr;
            float s0 = 0.f, s1 = 0.f;
#pragma unroll
            for (int nt = 0; nt < 4; nt++) {
                int c = wc * 32 + nt * 8 + (lane & 3) * 2;
                float v0 = acc[mt][nt][half * 2];
                float v1 = acc[mt][nt][half * 2 + 1];
                s0 += v0 * al[c] + v1 * al[c + 1];
                s1 += v0 * ar[c] + v1 * ar[c + 1];
                if (grow < N_NODES)
                    *(__half2*)&g_zh[grow * OUT_DIM + c] = __floats2half2_rn(v0, v1);
            }
            s0 += __shfl_xor_sync(0xffffffff, s0, 1);
            s0 += __shfl_xor_sync(0xffffffff, s0, 2);
            s1 += __shfl_xor_sync(0xffffffff, s1, 1);
            s1 += __shfl_xor_sync(0xffffffff, s1, 2);
            if ((lane & 3) == 0) {
                atomicAdd(&sS0[lr], s0);
                atomicAdd(&sS1[lr], s1);
            }
        }
    }
    __syncthreads();
    if (tid < 128) {
        int grow = r0 + tid;
        float s0 = sS0[tid], s1 = sS1[tid];
        if (grow < N_NODES) {
            g_ssrc[grow] = s0;
            g_sdst[grow] = s1;
        } else {
            s0 = __int_as_float(0xff800000);
            s1 = __int_as_float(0xff800000);
        }
#pragma unroll
        for (int o = 16; o > 0; o >>= 1) {
            s0 = fmaxf(s0, __shfl_xor_sync(0xffffffff, s0, o));
            s1 = fmaxf(s1, __shfl_xor_sync(0xffffffff, s1, o));
        }
        if ((tid & 31) == 0) {
            atomicMaxFloat(&g_maxs[0], s0);
            atomicMaxFloat(&g_maxs[1], s1);
        }
    }
}

// ---------------- single-pass scan with decoupled lookback ----------------------
__global__ void k_scan() {
    __shared__ int wsum[16];
    __shared__ int s_prefix;
    const int b = blockIdx.x, t = threadIdx.x;
    const int lane = t & 31, wid = t >> 5;
    const int i = b * SCAN_B + t;
    int v = (i < N_NODES) ? g_cnt[i] : 0;

    int x = v;
#pragma unroll
    for (int o = 1; o < 32; o <<= 1) {
        int y = __shfl_up_sync(0xffffffff, x, o);
        if (lane >= o) x += y;
    }
    if (lane == 31) wsum[wid] = x;
    __syncthreads();
    if (wid == 0) {
        int s = (lane < 16) ? wsum[lane] : 0;
#pragma unroll
        for (int o = 1; o < 16; o <<= 1) {
            int y = __shfl_up_sync(0xffffffff, s, o);
            if (lane >= o) s += y;
        }
        if (lane < 16) wsum[lane] = s;
    }
    __syncthreads();
    int incl = (wid ? wsum[wid - 1] : 0) + x;

    if (t == SCAN_B - 1) {
        unsigned long long pub = ((unsigned long long)incl << 2) | (b == 0 ? 2u : 1u);
        atomicExch(&g_scanstate[b], pub);
    }

    if (b > 0 && wid == 0) {
        long long run = 0;
        int j = b - 1;
        while (true) {
            int idx = j - lane;
            unsigned long long s;
            if (idx >= 0) {
                do { s = atomicAdd(&g_scanstate[idx], 0ull); } while ((s & 3) == 0);
            } else {
                s = 2ull;
            }
            unsigned mask = __ballot_sync(0xffffffff, (s & 3) == 2);
            long long contrib;
            if (mask) {
                int fl = __ffs(mask) - 1;
                contrib = (lane <= fl) ? (long long)(s >> 2) : 0;
            } else {
                contrib = (long long)(s >> 2);
            }
#pragma unroll
            for (int o = 16; o > 0; o >>= 1)
                contrib += __shfl_xor_sync(0xffffffff, contrib, o);
            run += contrib;
            if (mask) break;
            j -= 32;
        }
        if (lane == 0) s_prefix = (int)run;
    } else if (t == 0) {
        s_prefix = 0;
    }
    __syncthreads();
    int prefix = s_prefix;

    if (b > 0 && t == SCAN_B - 1)
        atomicExch(&g_scanstate[b], (((unsigned long long)(incl + prefix)) << 2) | 2u);

    if (i < N_NODES) {
        int o = prefix + incl - v;
        g_offcnt[i] = make_int2(o, v);   // packed (offset, degree)
        g_cur[i] = o;
    }
}

// 4 edges/thread: ex = exp(lrelu(ssrc[s]+sdst[d]) - M); scatter into CSR slots
__global__ void k_edge_fused() {
    int i = (blockIdx.x * blockDim.x + threadIdx.x) * 4;
    if (i >= N_EDGES) return;
    float M = g_maxs[0] + g_maxs[1];
    int4 a = *(const int4*)&g_sd[i];        // (s0,d0,s1,d1)
    int4 b = *(const int4*)&g_sd[i + 2];    // (s2,d2,s3,d3)
    float ss0 = g_ssrc[a.x], sd0 = g_sdst[a.y];
    float ss1 = g_ssrc[a.z], sd1 = g_sdst[a.w];
    float ss2 = g_ssrc[b.x], sd2 = g_sdst[b.y];
    float ss3 = g_ssrc[b.z], sd3 = g_sdst[b.w];
    float x0 = ss0 + sd0, x1 = ss1 + sd1, x2 = ss2 + sd2, x3 = ss3 + sd3;
    float e0 = x0 > 0.f ? x0 : NEG_SLOPE * x0;
    float e1 = x1 > 0.f ? x1 : NEG_SLOPE * x1;
    float e2 = x2 > 0.f ? x2 : NEG_SLOPE * x2;
    float e3 = x3 > 0.f ? x3 : NEG_SLOPE * x3;
    float ex0 = __expf(e0 - M);
    float ex1 = __expf(e1 - M);
    float ex2 = __expf(e2 - M);
    float ex3 = __expf(e3 - M);
    int p0 = atomicAdd(&g_cur[a.y], 1);
    g_edge[p0] = make_float2(ex0, __int_as_float(a.x));
    int p1 = atomicAdd(&g_cur[a.w], 1);
    g_edge[p1] = make_float2(ex1, __int_as_float(a.z));
    int p2 = atomicAdd(&g_cur[b.y], 1);
    g_edge[p2] = make_float2(ex2, __int_as_float(b.x));
    int p3 = atomicAdd(&g_cur[b.w], 1);
    g_edge[p3] = make_float2(ex3, __int_as_float(b.z));
}

// warp per node; all 32 lanes own disjoint half2 columns, no cross-lane reduce.
// (R9 form — empirically fastest; manual pipelining/unrolls all regressed.)
__global__ void k_aggregate(float* __restrict__ out) {
    int w    = (blockIdx.x * blockDim.x + threadIdx.x) >> 5;
    int lane = threadIdx.x & 31;
    if (w >= N_NODES) return;
    int2 oc = g_offcnt[w];               // one LDG.64: (offset, degree)
    int base = oc.x, deg = oc.y;
    const __half2* zrow = (const __half2*)g_zh;

    float ax = 0.f, ay = 0.f, wsum = 0.f;
    int j = 0;

#define ACC1(EX, SRCBITS) do {                                    \
        __half2 _z = zrow[__float_as_int(SRCBITS) * 32 + lane];   \
        float2 _f = __half22float2(_z);                            \
        ax += (EX) * _f.x; ay += (EX) * _f.y; wsum += (EX);        \
    } while (0)

    if ((base & 1) && deg > 0) {   // align base for float4 edge loads
        float2 ed = g_edge[base];
        ACC1(ed.x, ed.y);
        j = 1;
    }

    for (; j + 8 <= deg; j += 8) {
        const float4* ep = (const float4*)&g_edge[base + j];
        float4 ea = ep[0];
        float4 eb = ep[1];
        float4 ec = ep[2];
        float4 ed = ep[3];
        __half2 z0 = zrow[__float_as_int(ea.y) * 32 + lane];
        __half2 z1 = zrow[__float_as_int(ea.w) * 32 + lane];
        __half2 z2 = zrow[__float_as_int(eb.y) * 32 + lane];
        __half2 z3 = zrow[__float_as_int(eb.w) * 32 + lane];
        __half2 z4 = zrow[__float_as_int(ec.y) * 32 + lane];
        __half2 z5 = zrow[__float_as_int(ec.w) * 32 + lane];
        __half2 z6 = zrow[__float_as_int(ed.y) * 32 + lane];
        __half2 z7 = zrow[__float_as_int(ed.w) * 32 + lane];
        float2 f;
        f = __half22float2(z0); ax += ea.x * f.x; ay += ea.x * f.y;
        f = __half22float2(z1); ax += ea.z * f.x; ay += ea.z * f.y;
        f = __half22float2(z2); ax += eb.x * f.x; ay += eb.x * f.y;
        f = __half22float2(z3); ax += eb.z * f.x; ay += eb.z * f.y;
        f = __half22float2(z4); ax += ec.x * f.x; ay += ec.x * f.y;
        f = __half22float2(z5); ax += ec.z * f.x; ay += ec.z * f.y;
        f = __half22float2(z6); ax += ed.x * f.x; ay += ed.x * f.y;
        f = __half22float2(z7); ax += ed.z * f.x; ay += ed.z * f.y;
        wsum += (ea.x + ea.z) + (eb.x + eb.z) + (ec.x + ec.z) + (ed.x + ed.z);
    }
    if (j + 4 <= deg) {
        const float4* ep = (const float4*)&g_edge[base + j];
        float4 ea = ep[0];
        float4 eb = ep[1];
        __half2 z0 = zrow[__float_as_int(ea.y) * 32 + lane];
        __half2 z1 = zrow[__float_as_int(ea.w) * 32 + lane];
        __half2 z2 = zrow[__float_as_int(eb.y) * 32 + lane];
        __half2 z3 = zrow[__float_as_int(eb.w) * 32 + lane];
        float2 f;
        f = __half22float2(z0); ax += ea.x * f.x; ay += ea.x * f.y;
        f = __half22float2(z1); ax += ea.z * f.x; ay += ea.z * f.y;
        f = __half22float2(z2); ax += eb.x * f.x; ay += eb.x * f.y;
        f = __half22float2(z3); ax += eb.z * f.x; ay += eb.z * f.y;
        wsum += (ea.x + ea.z) + (eb.x + eb.z);
        j += 4;
    }
    for (; j < deg; j++) {
        float2 ed = g_edge[base + j];
        ACC1(ed.x, ed.y);
    }
#undef ACC1

    float inv = wsum > 0.f ? 1.f / wsum : 0.f;
    *(float2*)&out[w * OUT_DIM + lane * 2] = make_float2(ax * inv, ay * inv);
}

// ---------------- launch --------------------------------------------------------
extern "C" void kernel_launch(void* const* d_in, const int* in_sizes, int n_in,
                              void* d_out, int out_size) {
    const float* h = (const float*)d_in[0];
    const float* W = (const float*)d_in[1];
    const float* a = (const float*)d_in[2];
    const void*  ei = d_in[3];
    float* out = (float*)d_out;

    cudaFuncSetAttribute(k_fat, cudaFuncAttributeMaxDynamicSharedMemorySize, SMEM_TC_TOTAL);

    void* p_cnt = nullptr;
    void* p_maxs = nullptr;
    void* p_scan = nullptr;
    cudaGetSymbolAddress(&p_cnt, g_cnt);
    cudaGetSymbolAddress(&p_maxs, g_maxs);
    cudaGetSymbolAddress(&p_scan, g_scanstate);
    cudaMemsetAsync(p_cnt, 0, N_NODES * sizeof(int));
    cudaMemsetAsync(p_maxs, 0xFF, 2 * sizeof(float));
    cudaMemsetAsync(p_scan, 0, SCAN_NB * sizeof(unsigned long long));

    k_fat<<<NGB + NCB, 256, SMEM_TC_TOTAL>>>(h, W, a, ei);
    k_scan<<<SCAN_NB, SCAN_B>>>();
    k_edge_fused<<<(N_EDGES / 4 + 255) / 256, 256>>>();
    k_aggregate<<<(N_NODES * 32 + 255) / 256, 256>>>(out);
}

// round 13
// speedup vs baseline: 1.1952x; 1.0486x over previous
#include <cuda_runtime.h>
#include <cuda_bf16.h>
#include <cuda_fp16.h>
#include <cstdint>

#define N_NODES 100000
#define N_EDGES 1600000
#define IN_DIM  256
#define OUT_DIM 64
#define NEG_SLOPE 0.01f

#define SCAN_B 512
#define SCAN_NB 196   // 196*512 = 100352 >= N_NODES

#define NGB 782                         // gemm blocks (ceil(100000/128))
#define NCB ((N_EDGES + 1023) / 1024)   // convert blocks, 4 edges/thread

// SMEM map for fat kernel: double-buffered bf16 hi/lo tiles (SW128 swizzle)
#define B_AHI 0
#define B_ALO 16384
#define B_BHI 32768
#define B_BLO 40960
#define BUF_SZ 49152
#define OFF_ATT 98304
#define OFF_SS0 98816
#define OFF_SS1 99328
#define SMEM_TC_TOTAL 99840   // 2 CTAs/SM

// ---------------- scratch (device globals; no allocations allowed) ----------
// All globals are zero-init at module load; each launch restores that invariant
// for the next call (self-cleaning), so no memset nodes are needed.
__device__ __half  g_zh[N_NODES * OUT_DIM];   // z in fp16 (L2-resident, 12.8MB)
__device__ float   g_ssrc[N_NODES];
__device__ float   g_sdst[N_NODES];
__device__ int2    g_sd[N_EDGES];
__device__ float2  g_edge[N_EDGES];     // (ex, src) in CSR order
__device__ int     g_cnt[N_NODES];      // zero at entry; re-zeroed by k_scan
__device__ int2    g_offcnt[N_NODES];   // (offset, degree) packed: one LDG.64
__device__ int     g_cur[N_NODES];
__device__ float   g_maxs[2];           // 0.0 at entry; reset by k_aggregate
__device__ unsigned long long g_scanstate[SCAN_NB];  // zero at entry; re-zeroed by k_edge_fused

// ---------------- helpers ------------------------------------------------------
__device__ __forceinline__ uint32_t smem_to_u32(const void* p) {
    uint32_t a;
    asm("{ .reg .u64 t; cvta.to.shared.u64 t, %1; cvt.u32.u64 %0, t; }"
        : "=r"(a) : "l"(p));
    return a;
}
__device__ __forceinline__ uint32_t swzoff(int row, int colb) {
    uint32_t b = (uint32_t)(row * 128 + colb);
    return b ^ ((b >> 3) & 0x70);
}
__device__ __forceinline__ uint32_t pack_bf16(float a, float b) {
    uint32_t r;
    asm("{ .reg .b16 l, h;\n\t"
        "cvt.rn.bf16.f32 l, %1;\n\t"
        "cvt.rn.bf16.f32 h, %2;\n\t"
        "mov.b32 %0, {l, h}; }" : "=r"(r) : "f"(a), "f"(b));
    return r;
}
__device__ __forceinline__ float bf16lo_f(uint32_t v) { return __uint_as_float(v << 16); }
__device__ __forceinline__ float bf16hi_f(uint32_t v) { return __uint_as_float(v & 0xffff0000u); }

__device__ __forceinline__ void cvt_granule(const float4& p, const float4& q,
                                            uint4& hi, uint4& lo) {
    hi.x = pack_bf16(p.x, p.y);
    hi.y = pack_bf16(p.z, p.w);
    hi.z = pack_bf16(q.x, q.y);
    hi.w = pack_bf16(q.z, q.w);
    lo.x = pack_bf16(p.x - bf16lo_f(hi.x), p.y - bf16hi_f(hi.x));
    lo.y = pack_bf16(p.z - bf16lo_f(hi.y), p.w - bf16hi_f(hi.y));
    lo.z = pack_bf16(q.x - bf16lo_f(hi.z), q.y - bf16hi_f(hi.z));
    lo.w = pack_bf16(q.z - bf16lo_f(hi.w), q.w - bf16hi_f(hi.w));
}
__device__ __forceinline__ uint4 ldsm4(uint32_t addr) {
    uint4 r;
    asm volatile("ldmatrix.sync.aligned.m8n8.x4.shared.b16 {%0,%1,%2,%3}, [%4];"
        : "=r"(r.x), "=r"(r.y), "=r"(r.z), "=r"(r.w) : "r"(addr));
    return r;
}
__device__ __forceinline__ void mma_bf16(float* d, const uint4& A, uint32_t b0, uint32_t b1) {
    asm volatile("mma.sync.aligned.m16n8k16.row.col.f32.bf16.bf16.f32 "
        "{%0,%1,%2,%3}, {%4,%5,%6,%7}, {%8,%9}, {%0,%1,%2,%3};"
        : "+f"(d[0]), "+f"(d[1]), "+f"(d[2]), "+f"(d[3])
        : "r"(A.x), "r"(A.y), "r"(A.z), "r"(A.w), "r"(b0), "r"(b1));
}
__device__ __forceinline__ void atomicMaxFloat(float* addr, float v) {
    if (v >= 0.0f) atomicMax((int*)addr, __float_as_int(v));
    else           atomicMin((unsigned int*)addr, (unsigned int)__float_as_int(v));
}

// ---- GEMM building blocks ----
__device__ __forceinline__ void ldg_chunk(const float* __restrict__ h,
                                          const float* __restrict__ W,
                                          int r0, int k0, int tid,
                                          float4 fa[4][2], float4 fb[2][2]) {
#pragma unroll
    for (int j = 0; j < 4; j++) {
        int g = tid + j * 256;
        int row = g >> 3, c8 = g & 7;
        int gr = r0 + row;
        if (gr < N_NODES) {
            fa[j][0] = *(const float4*)&h[gr * IN_DIM + k0 + c8 * 8];
            fa[j][1] = *(const float4*)&h[gr * IN_DIM + k0 + c8 * 8 + 4];
        } else {
            fa[j][0] = make_float4(0.f, 0.f, 0.f, 0.f);
            fa[j][1] = make_float4(0.f, 0.f, 0.f, 0.f);
        }
    }
#pragma unroll
    for (int j = 0; j < 2; j++) {
        int g = tid + j * 256;
        int row = g >> 3, c8 = g & 7;
        fb[j][0] = *(const float4*)&W[row * IN_DIM + k0 + c8 * 8];
        fb[j][1] = *(const float4*)&W[row * IN_DIM + k0 + c8 * 8 + 4];
    }
}

__device__ __forceinline__ void cvt_sts(char* smem, int bufbase, int tid,
                                        const float4 fa[4][2], const float4 fb[2][2]) {
#pragma unroll
    for (int j = 0; j < 4; j++) {
        int g = tid + j * 256;
        int row = g >> 3, c8 = g & 7;
        uint4 hi, lo;
        cvt_granule(fa[j][0], fa[j][1], hi, lo);
        uint32_t off = swzoff(row, c8 * 16);
        *(uint4*)(smem + bufbase + B_AHI + off) = hi;
        *(uint4*)(smem + bufbase + B_ALO + off) = lo;
    }
#pragma unroll
    for (int j = 0; j < 2; j++) {
        int g = tid + j * 256;
        int row = g >> 3, c8 = g & 7;
        uint4 hi, lo;
        cvt_granule(fb[j][0], fb[j][1], hi, lo);
        uint32_t off = swzoff(row, c8 * 16);
        *(uint4*)(smem + bufbase + B_BHI + off) = hi;
        *(uint4*)(smem + bufbase + B_BLO + off) = lo;
    }
}

__device__ __forceinline__ void mma_chunk(uint32_t sbuf, int wr, int wc, int lane,
                                          float acc[2][4][4]) {
#pragma unroll
    for (int ks = 0; ks < 4; ks++) {
        uint4 Ah[2], Al[2], Bh[2], Bl[2];
        int arow  = wr * 32 + (lane & 15);
        int acolb = ks * 32 + ((lane >> 4) << 4);
#pragma unroll
        for (int mt = 0; mt < 2; mt++) {
            uint32_t ad = sbuf + B_AHI + swzoff(arow + mt * 16, acolb);
            Ah[mt] = ldsm4(ad);
            Al[mt] = ldsm4(ad + (B_ALO - B_AHI));
        }
        int brow  = wc * 32 + (lane & 7) + ((lane >> 4) << 3);
        int bcolb = ks * 32 + (((lane >> 3) & 1) << 4);
#pragma unroll
        for (int nb = 0; nb < 2; nb++) {
            uint32_t bd = sbuf + B_BHI + swzoff(brow + nb * 16, bcolb);
            Bh[nb] = ldsm4(bd);
            Bl[nb] = ldsm4(bd + (B_BLO - B_BHI));
        }
#pragma unroll
        for (int mt = 0; mt < 2; mt++)
#pragma unroll
            for (int nb = 0; nb < 2; nb++) {
                mma_bf16(acc[mt][nb * 2],     Ah[mt], Bh[nb].x, Bh[nb].y);
                mma_bf16(acc[mt][nb * 2 + 1], Ah[mt], Bh[nb].z, Bh[nb].w);
                mma_bf16(acc[mt][nb * 2],     Al[mt], Bh[nb].x, Bh[nb].y);
                mma_bf16(acc[mt][nb * 2 + 1], Al[mt], Bh[nb].z, Bh[nb].w);
                mma_bf16(acc[mt][nb * 2],     Ah[mt], Bl[nb].x, Bl[nb].y);
                mma_bf16(acc[mt][nb * 2 + 1], Ah[mt], Bl[nb].z, Bl[nb].w);
            }
    }
}

// ---------------- fat kernel: GEMM blocks [0, NGB) + convert blocks [NGB, ...) ---
__global__ __launch_bounds__(256, 2) void k_fat(const float* __restrict__ h,
                                                const float* __restrict__ W,
                                                const float* __restrict__ a_attn,
                                                const void* __restrict__ ei) {
    extern __shared__ char smem[];
    const int bid = blockIdx.x;
    const int tid = threadIdx.x;

    if (bid >= NGB) {
        __shared__ int s_flag;
        if (tid < 32) {
            const long long* p = (const long long*)ei;
            long long v = p[tid];
            int ok = (v >= 0 && v < N_NODES);
            unsigned m = __ballot_sync(0xffffffff, ok);
            if (tid == 0) s_flag = (m == 0xffffffffu);
        }
        __syncthreads();
        int base = (bid - NGB) * 1024 + tid * 4;
        if (base + 3 >= N_EDGES) return;
        int s0, s1, s2, s3, d0, d1, d2, d3;
        if (s_flag) {
            const long long* p = (const long long*)ei;
            longlong2 a = *(const longlong2*)(p + base);
            longlong2 b = *(const longlong2*)(p + base + 2);
            longlong2 c = *(const longlong2*)(p + N_EDGES + base);
            longlong2 d = *(const longlong2*)(p + N_EDGES + base + 2);
            s0 = (int)a.x; s1 = (int)a.y; s2 = (int)b.x; s3 = (int)b.y;
            d0 = (int)c.x; d1 = (int)c.y; d2 = (int)d.x; d3 = (int)d.y;
        } else {
            const int* p = (const int*)ei;
            int4 a = *(const int4*)(p + base);
            int4 c = *(const int4*)(p + N_EDGES + base);
            s0 = a.x; s1 = a.y; s2 = a.z; s3 = a.w;
            d0 = c.x; d1 = c.y; d2 = c.z; d3 = c.w;
        }
        *(int4*)&g_sd[base]     = make_int4(s0, d0, s1, d1);
        *(int4*)&g_sd[base + 2] = make_int4(s2, d2, s3, d3);
        atomicAdd(&g_cnt[d0], 1);
        atomicAdd(&g_cnt[d1], 1);
        atomicAdd(&g_cnt[d2], 1);
        atomicAdd(&g_cnt[d3], 1);
        return;
    }

    // ---------------- GEMM path ----------------
    const uint32_t sb = smem_to_u32(smem);
    const int lane = tid & 31, wid = tid >> 5;
    const int wr = wid & 3, wc = wid >> 2;
    const int r0 = bid * 128;

    float* sS0 = (float*)(smem + OFF_SS0);
    float* sS1 = (float*)(smem + OFF_SS1);
    if (tid < 128) {
        ((float*)(smem + OFF_ATT))[tid] = a_attn[tid];
        sS0[tid] = 0.f;
        sS1[tid] = 0.f;
    }

    float acc[2][4][4];
#pragma unroll
    for (int a = 0; a < 2; a++)
#pragma unroll
        for (int b = 0; b < 4; b++)
#pragma unroll
            for (int c = 0; c < 4; c++) acc[a][b][c] = 0.f;

    float4 fa[4][2], fb[2][2];
    ldg_chunk(h, W, r0, 0, tid, fa, fb);
    cvt_sts(smem, 0, tid, fa, fb);
    __syncthreads();

#pragma unroll
    for (int it = 1; it < 4; it++) {
        ldg_chunk(h, W, r0, it * 64, tid, fa, fb);
        mma_chunk(sb + ((it - 1) & 1) * BUF_SZ, wr, wc, lane, acc);
        cvt_sts(smem, (it & 1) * BUF_SZ, tid, fa, fb);
        __syncthreads();
    }
    mma_chunk(sb + BUF_SZ, wr, wc, lane, acc);

    const float* al = (const float*)(smem + OFF_ATT);
    const float* ar = al + OUT_DIM;
#pragma unroll
    for (int mt = 0; mt < 2; mt++) {
#pragma unroll
        for (int half = 0; half < 2; half++) {
            int lr = wr * 32 + mt * 16 + (lane >> 2) + half * 8;
            int grow = r0 + lr;
            float s0 = 0.f, s1 = 0.f;
#pragma unroll
            for (int nt = 0; nt < 4; nt++) {
                int c = wc * 32 + nt * 8 + (lane & 3) * 2;
                float v0 = acc[mt][nt][half * 2];
                float v1 = acc[mt][nt][half * 2 + 1];
                s0 += v0 * al[c] + v1 * al[c + 1];
                s1 += v0 * ar[c] + v1 * ar[c + 1];
                if (grow < N_NODES)
                    *(__half2*)&g_zh[grow * OUT_DIM + c] = __floats2half2_rn(v0, v1);
            }
            s0 += __shfl_xor_sync(0xffffffff, s0, 1);
            s0 += __shfl_xor_sync(0xffffffff, s0, 2);
            s1 += __shfl_xor_sync(0xffffffff, s1, 1);
            s1 += __shfl_xor_sync(0xffffffff, s1, 2);
            if ((lane & 3) == 0) {
                atomicAdd(&sS0[lr], s0);
                atomicAdd(&sS1[lr], s1);
            }
        }
    }
    __syncthreads();
    if (tid < 128) {
        int grow = r0 + tid;
        float s0 = sS0[tid], s1 = sS1[tid];
        if (grow < N_NODES) {
            g_ssrc[grow] = s0;
            g_sdst[grow] = s1;
        } else {
            s0 = __int_as_float(0xff800000);
            s1 = __int_as_float(0xff800000);
        }
#pragma unroll
        for (int o = 16; o > 0; o >>= 1) {
            s0 = fmaxf(s0, __shfl_xor_sync(0xffffffff, s0, o));
            s1 = fmaxf(s1, __shfl_xor_sync(0xffffffff, s1, o));
        }
        if ((tid & 31) == 0) {
            atomicMaxFloat(&g_maxs[0], s0);
            atomicMaxFloat(&g_maxs[1], s1);
        }
    }
}

// ---------------- single-pass scan with decoupled lookback ----------------------
// Also re-zeroes g_cnt for the next launch (self-cleaning).
__global__ void k_scan() {
    __shared__ int wsum[16];
    __shared__ int s_prefix;
    const int b = blockIdx.x, t = threadIdx.x;
    const int lane = t & 31, wid = t >> 5;
    const int i = b * SCAN_B + t;
    int v = (i < N_NODES) ? g_cnt[i] : 0;
    if (i < N_NODES) g_cnt[i] = 0;       // restore zero-init invariant

    int x = v;
#pragma unroll
    for (int o = 1; o < 32; o <<= 1) {
        int y = __shfl_up_sync(0xffffffff, x, o);
        if (lane >= o) x += y;
    }
    if (lane == 31) wsum[wid] = x;
    __syncthreads();
    if (wid == 0) {
        int s = (lane < 16) ? wsum[lane] : 0;
#pragma unroll
        for (int o = 1; o < 16; o <<= 1) {
            int y = __shfl_up_sync(0xffffffff, s, o);
            if (lane >= o) s += y;
        }
        if (lane < 16) wsum[lane] = s;
    }
    __syncthreads();
    int incl = (wid ? wsum[wid - 1] : 0) + x;

    if (t == SCAN_B - 1) {
        unsigned long long pub = ((unsigned long long)incl << 2) | (b == 0 ? 2u : 1u);
        atomicExch(&g_scanstate[b], pub);
    }

    if (b > 0 && wid == 0) {
        long long run = 0;
        int j = b - 1;
        while (true) {
            int idx = j - lane;
            unsigned long long s;
            if (idx >= 0) {
                do { s = atomicAdd(&g_scanstate[idx], 0ull); } while ((s & 3) == 0);
            } else {
                s = 2ull;
            }
            unsigned mask = __ballot_sync(0xffffffff, (s & 3) == 2);
            long long contrib;
            if (mask) {
                int fl = __ffs(mask) - 1;
                contrib = (lane <= fl) ? (long long)(s >> 2) : 0;
            } else {
                contrib = (long long)(s >> 2);
            }
#pragma unroll
            for (int o = 16; o > 0; o >>= 1)
                contrib += __shfl_xor_sync(0xffffffff, contrib, o);
            run += contrib;
            if (mask) break;
            j -= 32;
        }
        if (lane == 0) s_prefix = (int)run;
    } else if (t == 0) {
        s_prefix = 0;
    }
    __syncthreads();
    int prefix = s_prefix;

    if (b > 0 && t == SCAN_B - 1)
        atomicExch(&g_scanstate[b], (((unsigned long long)(incl + prefix)) << 2) | 2u);

    if (i < N_NODES) {
        int o = prefix + incl - v;
        g_offcnt[i] = make_int2(o, v);   // packed (offset, degree)
        g_cur[i] = o;
    }
}

// 2 edges/thread (R9 form): ex = exp(lrelu(ssrc[s]+sdst[d]) - M); CSR scatter.
// Also re-zeroes g_scanstate (k_scan is complete once this kernel starts).
__global__ void k_edge_fused() {
    if (blockIdx.x == 0 && threadIdx.x < SCAN_NB)
        g_scanstate[threadIdx.x] = 0ull;   // restore zero-init invariant
    int i = (blockIdx.x * blockDim.x + threadIdx.x) * 2;
    if (i >= N_EDGES) return;
    float M = g_maxs[0] + g_maxs[1];
    int4 sd2 = *(const int4*)&g_sd[i];     // (s0,d0,s1,d1)
    float x0 = g_ssrc[sd2.x] + g_sdst[sd2.y];
    float x1 = g_ssrc[sd2.z] + g_sdst[sd2.w];
    float e0 = x0 > 0.f ? x0 : NEG_SLOPE * x0;
    float e1 = x1 > 0.f ? x1 : NEG_SLOPE * x1;
    float ex0 = __expf(e0 - M);
    float ex1 = __expf(e1 - M);
    int p0 = atomicAdd(&g_cur[sd2.y], 1);
    g_edge[p0] = make_float2(ex0, __int_as_float(sd2.x));
    int p1 = atomicAdd(&g_cur[sd2.w], 1);
    g_edge[p1] = make_float2(ex1, __int_as_float(sd2.z));
}

// warp per node; all 32 lanes own disjoint half2 columns, no cross-lane reduce.
// (R9 form — empirically fastest.) Also resets g_maxs to 0.0f = module-load
// state; M = max(0, true max) is a valid softmax shift every call, so outputs
// are deterministic across calls.
__global__ void k_aggregate(float* __restrict__ out) {
    if (blockIdx.x == 0 && threadIdx.x < 2)
        g_maxs[threadIdx.x] = 0.f;        // restore zero-init invariant
    int w    = (blockIdx.x * blockDim.x + threadIdx.x) >> 5;
    int lane = threadIdx.x & 31;
    if (w >= N_NODES) return;
    int2 oc = g_offcnt[w];               // one LDG.64: (offset, degree)
    int base = oc.x, deg = oc.y;
    const __half2* zrow = (const __half2*)g_zh;

    float ax = 0.f, ay = 0.f, wsum = 0.f;
    int j = 0;

#define ACC1(EX, SRCBITS) do {                                    \
        __half2 _z = zrow[__float_as_int(SRCBITS) * 32 + lane];   \
        float2 _f = __half22float2(_z);                            \
        ax += (EX) * _f.x; ay += (EX) * _f.y; wsum += (EX);        \
    } while (0)

    if ((base & 1) && deg > 0) {   // align base for float4 edge loads
        float2 ed = g_edge[base];
        ACC1(ed.x, ed.y);
        j = 1;
    }

    for (; j + 8 <= deg; j += 8) {
        const float4* ep = (const float4*)&g_edge[base + j];
        float4 ea = ep[0];
        float4 eb = ep[1];
        float4 ec = ep[2];
        float4 ed = ep[3];
        __half2 z0 = zrow[__float_as_int(ea.y) * 32 + lane];
        __half2 z1 = zrow[__float_as_int(ea.w) * 32 + lane];
        __half2 z2 = zrow[__float_as_int(eb.y) * 32 + lane];
        __half2 z3 = zrow[__float_as_int(eb.w) * 32 + lane];
        __half2 z4 = zrow[__float_as_int(ec.y) * 32 + lane];
        __half2 z5 = zrow[__float_as_int(ec.w) * 32 + lane];
        __half2 z6 = zrow[__float_as_int(ed.y) * 32 + lane];
        __half2 z7 = zrow[__float_as_int(ed.w) * 32 + lane];
        float2 f;
        f = __half22float2(z0); ax += ea.x * f.x; ay += ea.x * f.y;
        f = __half22float2(z1); ax += ea.z * f.x; ay += ea.z * f.y;
        f = __half22float2(z2); ax += eb.x * f.x; ay += eb.x * f.y;
        f = __half22float2(z3); ax += eb.z * f.x; ay += eb.z * f.y;
        f = __half22float2(z4); ax += ec.x * f.x; ay += ec.x * f.y;
        f = __half22float2(z5); ax += ec.z * f.x; ay += ec.z * f.y;
        f = __half22float2(z6); ax += ed.x * f.x; ay += ed.x * f.y;
        f = __half22float2(z7); ax += ed.z * f.x; ay += ed.z * f.y;
        wsum += (ea.x + ea.z) + (eb.x + eb.z) + (ec.x + ec.z) + (ed.x + ed.z);
    }
    if (j + 4 <= deg) {
        const float4* ep = (const float4*)&g_edge[base + j];
        float4 ea = ep[0];
        float4 eb = ep[1];
        __half2 z0 = zrow[__float_as_int(ea.y) * 32 + lane];
        __half2 z1 = zrow[__float_as_int(ea.w) * 32 + lane];
        __half2 z2 = zrow[__float_as_int(eb.y) * 32 + lane];
        __half2 z3 = zrow[__float_as_int(eb.w) * 32 + lane];
        float2 f;
        f = __half22float2(z0); ax += ea.x * f.x; ay += ea.x * f.y;
        f = __half22float2(z1); ax += ea.z * f.x; ay += ea.z * f.y;
        f = __half22float2(z2); ax += eb.x * f.x; ay += eb.x * f.y;
        f = __half22float2(z3); ax += eb.z * f.x; ay += eb.z * f.y;
        wsum += (ea.x + ea.z) + (eb.x + eb.z);
        j += 4;
    }
    for (; j < deg; j++) {
        float2 ed = g_edge[base + j];
        ACC1(ed.x, ed.y);
    }
#undef ACC1

    float inv = wsum > 0.f ? 1.f / wsum : 0.f;
    *(float2*)&out[w * OUT_DIM + lane * 2] = make_float2(ax * inv, ay * inv);
}

// ---------------- launch --------------------------------------------------------
extern "C" void kernel_launch(void* const* d_in, const int* in_sizes, int n_in,
                              void* d_out, int out_size) {
    const float* h = (const float*)d_in[0];
    const float* W = (const float*)d_in[1];
    const float* a = (const float*)d_in[2];
    const void*  ei = d_in[3];
    float* out = (float*)d_out;

    cudaFuncSetAttribute(k_fat, cudaFuncAttributeMaxDynamicSharedMemorySize, SMEM_TC_TOTAL);

    k_fat<<<NGB + NCB, 256, SMEM_TC_TOTAL>>>(h, W, a, ei);
    k_scan<<<SCAN_NB, SCAN_B>>>();
    k_edge_fused<<<(N_EDGES / 2 + 255) / 256, 256>>>();
    k_aggregate<<<(N_NODES * 32 + 255) / 256, 256>>>(out);
}

// round 14
// speedup vs baseline: 1.2342x; 1.0326x over previous
#include <cuda_runtime.h>
#include <cuda_bf16.h>
#include <cuda_fp16.h>
#include <cstdint>

#define N_NODES 100000
#define N_EDGES 1600000
#define IN_DIM  256
#define OUT_DIM 64
#define NEG_SLOPE 0.01f

#define SCAN_B 512
#define SCAN_NB 196   // 196*512 = 100352 >= N_NODES

#define NGB 782                         // gemm blocks (ceil(100000/128))
#define NCB ((N_EDGES + 1023) / 1024)   // convert blocks, 4 edges/thread

// SMEM map for fat kernel: double-buffered bf16 hi/lo tiles (SW128 swizzle)
#define B_AHI 0
#define B_ALO 16384
#define B_BHI 32768
#define B_BLO 40960
#define BUF_SZ 49152
#define OFF_ATT 98304
#define OFF_SS0 98816
#define OFF_SS1 99328
#define SMEM_TC_TOTAL 99840   // 2 CTAs/SM

// ---------------- scratch (device globals; no allocations allowed) ----------
// Zero-init at module load; each launch restores that invariant (self-cleaning).
__device__ __half  g_zh[N_NODES * OUT_DIM];   // z in fp16 (L2-resident, 12.8MB)
__device__ float   g_ssrc[N_NODES];
__device__ float   g_sdst[N_NODES];
__device__ float2  g_edge[N_EDGES + N_NODES]; // (ex, src) CSR order, even-aligned bases
__device__ int     g_cnt[N_NODES];      // zero at entry; re-zeroed by k_scan
__device__ int2    g_offcnt[N_NODES];   // (even offset, degree): one LDG.64
__device__ int     g_cur[N_NODES];
__device__ float   g_maxs[2];           // 0.0 at entry; reset by k_aggregate
__device__ int     g_flag;              // edge_index dtype: 1 = int64, 0 = int32
__device__ unsigned long long g_scanstate[SCAN_NB];  // zeroed by k_edge_fused

// ---------------- helpers ------------------------------------------------------
__device__ __forceinline__ uint32_t smem_to_u32(const void* p) {
    uint32_t a;
    asm("{ .reg .u64 t; cvta.to.shared.u64 t, %1; cvt.u32.u64 %0, t; }"
        : "=r"(a) : "l"(p));
    return a;
}
__device__ __forceinline__ uint32_t swzoff(int row, int colb) {
    uint32_t b = (uint32_t)(row * 128 + colb);
    return b ^ ((b >> 3) & 0x70);
}
__device__ __forceinline__ uint32_t pack_bf16(float a, float b) {
    uint32_t r;
    asm("{ .reg .b16 l, h;\n\t"
        "cvt.rn.bf16.f32 l, %1;\n\t"
        "cvt.rn.bf16.f32 h, %2;\n\t"
        "mov.b32 %0, {l, h}; }" : "=r"(r) : "f"(a), "f"(b));
    return r;
}
__device__ __forceinline__ float bf16lo_f(uint32_t v) { return __uint_as_float(v << 16); }
__device__ __forceinline__ float bf16hi_f(uint32_t v) { return __uint_as_float(v & 0xffff0000u); }

__device__ __forceinline__ void cvt_granule(const float4& p, const float4& q,
                                            uint4& hi, uint4& lo) {
    hi.x = pack_bf16(p.x, p.y);
    hi.y = pack_bf16(p.z, p.w);
    hi.z = pack_bf16(q.x, q.y);
    hi.w = pack_bf16(q.z, q.w);
    lo.x = pack_bf16(p.x - bf16lo_f(hi.x), p.y - bf16hi_f(hi.x));
    lo.y = pack_bf16(p.z - bf16lo_f(hi.y), p.w - bf16hi_f(hi.y));
    lo.z = pack_bf16(q.x - bf16lo_f(hi.z), q.y - bf16hi_f(hi.z));
    lo.w = pack_bf16(q.z - bf16lo_f(hi.w), q.w - bf16hi_f(hi.w));
}
__device__ __forceinline__ uint4 ldsm4(uint32_t addr) {
    uint4 r;
    asm volatile("ldmatrix.sync.aligned.m8n8.x4.shared.b16 {%0,%1,%2,%3}, [%4];"
        : "=r"(r.x), "=r"(r.y), "=r"(r.z), "=r"(r.w) : "r"(addr));
    return r;
}
__device__ __forceinline__ void mma_bf16(float* d, const uint4& A, uint32_t b0, uint32_t b1) {
    asm volatile("mma.sync.aligned.m16n8k16.row.col.f32.bf16.bf16.f32 "
        "{%0,%1,%2,%3}, {%4,%5,%6,%7}, {%8,%9}, {%0,%1,%2,%3};"
        : "+f"(d[0]), "+f"(d[1]), "+f"(d[2]), "+f"(d[3])
        : "r"(A.x), "r"(A.y), "r"(A.z), "r"(A.w), "r"(b0), "r"(b1));
}
__device__ __forceinline__ void atomicMaxFloat(float* addr, float v) {
    if (v >= 0.0f) atomicMax((int*)addr, __float_as_int(v));
    else           atomicMin((unsigned int*)addr, (unsigned int)__float_as_int(v));
}

// ---- GEMM building blocks ----
__device__ __forceinline__ void ldg_chunk(const float* __restrict__ h,
                                          const float* __restrict__ W,
                                          int r0, int k0, int tid,
                                          float4 fa[4][2], float4 fb[2][2]) {
#pragma unroll
    for (int j = 0; j < 4; j++) {
        int g = tid + j * 256;
        int row = g >> 3, c8 = g & 7;
        int gr = r0 + row;
        if (gr < N_NODES) {
            fa[j][0] = __ldg((const float4*)&h[gr * IN_DIM + k0 + c8 * 8]);
            fa[j][1] = __ldg((const float4*)&h[gr * IN_DIM + k0 + c8 * 8 + 4]);
        } else {
            fa[j][0] = make_float4(0.f, 0.f, 0.f, 0.f);
            fa[j][1] = make_float4(0.f, 0.f, 0.f, 0.f);
        }
    }
#pragma unroll
    for (int j = 0; j < 2; j++) {
        int g = tid + j * 256;
        int row = g >> 3, c8 = g & 7;
        fb[j][0] = __ldg((const float4*)&W[row * IN_DIM + k0 + c8 * 8]);
        fb[j][1] = __ldg((const float4*)&W[row * IN_DIM + k0 + c8 * 8 + 4]);
    }
}

__device__ __forceinline__ void cvt_sts(char* smem, int bufbase, int tid,
                                        const float4 fa[4][2], const float4 fb[2][2]) {
#pragma unroll
    for (int j = 0; j < 4; j++) {
        int g = tid + j * 256;
        int row = g >> 3, c8 = g & 7;
        uint4 hi, lo;
        cvt_granule(fa[j][0], fa[j][1], hi, lo);
        uint32_t off = swzoff(row, c8 * 16);
        *(uint4*)(smem + bufbase + B_AHI + off) = hi;
        *(uint4*)(smem + bufbase + B_ALO + off) = lo;
    }
#pragma unroll
    for (int j = 0; j < 2; j++) {
        int g = tid + j * 256;
        int row = g >> 3, c8 = g & 7;
        uint4 hi, lo;
        cvt_granule(fb[j][0], fb[j][1], hi, lo);
        uint32_t off = swzoff(row, c8 * 16);
        *(uint4*)(smem + bufbase + B_BHI + off) = hi;
        *(uint4*)(smem + bufbase + B_BLO + off) = lo;
    }
}

__device__ __forceinline__ void mma_chunk(uint32_t sbuf, int wr, int wc, int lane,
                                          float acc[2][4][4]) {
#pragma unroll
    for (int ks = 0; ks < 4; ks++) {
        uint4 Ah[2], Al[2], Bh[2], Bl[2];
        int arow  = wr * 32 + (lane & 15);
        int acolb = ks * 32 + ((lane >> 4) << 4);
#pragma unroll
        for (int mt = 0; mt < 2; mt++) {
            uint32_t ad = sbuf + B_AHI + swzoff(arow + mt * 16, acolb);
            Ah[mt] = ldsm4(ad);
            Al[mt] = ldsm4(ad + (B_ALO - B_AHI));
        }
        int brow  = wc * 32 + (lane & 7) + ((lane >> 4) << 3);
        int bcolb = ks * 32 + (((lane >> 3) & 1) << 4);
#pragma unroll
        for (int nb = 0; nb < 2; nb++) {
            uint32_t bd = sbuf + B_BHI + swzoff(brow + nb * 16, bcolb);
            Bh[nb] = ldsm4(bd);
            Bl[nb] = ldsm4(bd + (B_BLO - B_BHI));
        }
#pragma unroll
        for (int mt = 0; mt < 2; mt++)
#pragma unroll
            for (int nb = 0; nb < 2; nb++) {
                mma_bf16(acc[mt][nb * 2],     Ah[mt], Bh[nb].x, Bh[nb].y);
                mma_bf16(acc[mt][nb * 2 + 1], Ah[mt], Bh[nb].z, Bh[nb].w);
                mma_bf16(acc[mt][nb * 2],     Al[mt], Bh[nb].x, Bh[nb].y);
                mma_bf16(acc[mt][nb * 2 + 1], Al[mt], Bh[nb].z, Bh[nb].w);
                mma_bf16(acc[mt][nb * 2],     Ah[mt], Bl[nb].x, Bl[nb].y);
                mma_bf16(acc[mt][nb * 2 + 1], Ah[mt], Bl[nb].z, Bl[nb].w);
            }
    }
}

// ---------------- fat kernel: GEMM blocks [0, NGB) + convert blocks [NGB, ...) ---
__global__ __launch_bounds__(256, 2) void k_fat(const float* __restrict__ h,
                                                const float* __restrict__ W,
                                                const float* __restrict__ a_attn,
                                                const void* __restrict__ ei) {
    extern __shared__ char smem[];
    const int bid = blockIdx.x;
    const int tid = threadIdx.x;

    if (bid >= NGB) {
        // ---- convert path: count degrees only (edge_fused re-reads ei) ----
        __shared__ int s_flag;
        if (tid < 32) {
            const long long* p = (const long long*)ei;
            long long v = __ldg(&p[tid]);
            int ok = (v >= 0 && v < N_NODES);
            unsigned m = __ballot_sync(0xffffffff, ok);
            if (tid == 0) {
                s_flag = (m == 0xffffffffu);
                if (bid == NGB) g_flag = s_flag;   // publish dtype for edge_fused
            }
        }
        __syncthreads();
        int base = (bid - NGB) * 1024 + tid * 4;
        if (base + 3 >= N_EDGES) return;
        int d0, d1, d2, d3;
        if (s_flag) {
            const long long* p = (const long long*)ei;
            longlong2 c = __ldg((const longlong2*)(p + N_EDGES + base));
            longlong2 d = __ldg((const longlong2*)(p + N_EDGES + base + 2));
            d0 = (int)c.x; d1 = (int)c.y; d2 = (int)d.x; d3 = (int)d.y;
        } else {
            const int* p = (const int*)ei;
            int4 c = __ldg((const int4*)(p + N_EDGES + base));
            d0 = c.x; d1 = c.y; d2 = c.z; d3 = c.w;
        }
        atomicAdd(&g_cnt[d0], 1);
        atomicAdd(&g_cnt[d1], 1);
        atomicAdd(&g_cnt[d2], 1);
        atomicAdd(&g_cnt[d3], 1);
        return;
    }

    // ---------------- GEMM path ----------------
    const uint32_t sb = smem_to_u32(smem);
    const int lane = tid & 31, wid = tid >> 5;
    const int wr = wid & 3, wc = wid >> 2;
    const int r0 = bid * 128;

    float* sS0 = (float*)(smem + OFF_SS0);
    float* sS1 = (float*)(smem + OFF_SS1);
    if (tid < 128) {
        ((float*)(smem + OFF_ATT))[tid] = a_attn[tid];
        sS0[tid] = 0.f;
        sS1[tid] = 0.f;
    }

    float acc[2][4][4];
#pragma unroll
    for (int a = 0; a < 2; a++)
#pragma unroll
        for (int b = 0; b < 4; b++)
#pragma unroll
            for (int c = 0; c < 4; c++) acc[a][b][c] = 0.f;

    float4 fa[4][2], fb[2][2];
    ldg_chunk(h, W, r0, 0, tid, fa, fb);
    cvt_sts(smem, 0, tid, fa, fb);
    __syncthreads();

#pragma unroll
    for (int it = 1; it < 4; it++) {
        ldg_chunk(h, W, r0, it * 64, tid, fa, fb);
        mma_chunk(sb + ((it - 1) & 1) * BUF_SZ, wr, wc, lane, acc);
        cvt_sts(smem, (it & 1) * BUF_SZ, tid, fa, fb);
        __syncthreads();
    }
    mma_chunk(sb + BUF_SZ, wr, wc, lane, acc);

    const float* al = (const float*)(smem + OFF_ATT);
    const float* ar = al + OUT_DIM;
#pragma unroll
    for (int mt = 0; mt < 2; mt++) {
#pragma unroll
        for (int half = 0; half < 2; half++) {
            int lr = wr * 32 + mt * 16 + (lane >> 2) + half * 8;
            int grow = r0 + lr;
            float s0 = 0.f, s1 = 0.f;
#pragma unroll
            for (int nt = 0; nt < 4; nt++) {
                int c = wc * 32 + nt * 8 + (lane & 3) * 2;
                float v0 = acc[mt][nt][half * 2];
                float v1 = acc[mt][nt][half * 2 + 1];
                s0 += v0 * al[c] + v1 * al[c + 1];
                s1 += v0 * ar[c] + v1 * ar[c + 1];
                if (grow < N_NODES)
                    *(__half2*)&g_zh[grow * OUT_DIM + c] = __floats2half2_rn(v0, v1);
            }
            s0 += __shfl_xor_sync(0xffffffff, s0, 1);
            s0 += __shfl_xor_sync(0xffffffff, s0, 2);
            s1 += __shfl_xor_sync(0xffffffff, s1, 1);
            s1 += __shfl_xor_sync(0xffffffff, s1, 2);
            if ((lane & 3) == 0) {
                atomicAdd(&sS0[lr], s0);
                atomicAdd(&sS1[lr], s1);
            }
        }
    }
    __syncthreads();
    if (tid < 128) {
        int grow = r0 + tid;
        float s0 = sS0[tid], s1 = sS1[tid];
        if (grow < N_NODES) {
            g_ssrc[grow] = s0;
            g_sdst[grow] = s1;
        } else {
            s0 = __int_as_float(0xff800000);
            s1 = __int_as_float(0xff800000);
        }
#pragma unroll
        for (int o = 16; o > 0; o >>= 1) {
            s0 = fmaxf(s0, __shfl_xor_sync(0xffffffff, s0, o));
            s1 = fmaxf(s1, __shfl_xor_sync(0xffffffff, s1, o));
        }
        if ((tid & 31) == 0) {
            atomicMaxFloat(&g_maxs[0], s0);
            atomicMaxFloat(&g_maxs[1], s1);
        }
    }
}

// ---------------- single-pass scan with decoupled lookback ----------------------
// Scans even-rounded degrees (deg + (deg&1)) so every CSR base is 16B-aligned.
// Also re-zeroes g_cnt for the next launch.
__global__ void k_scan() {
    __shared__ int wsum[16];
    __shared__ int s_prefix;
    const int b = blockIdx.x, t = threadIdx.x;
    const int lane = t & 31, wid = t >> 5;
    const int i = b * SCAN_B + t;
    int v = (i < N_NODES) ? g_cnt[i] : 0;
    if (i < N_NODES) g_cnt[i] = 0;       // restore zero-init invariant
    int ve = v + (v & 1);                // even-rounded for aligned bases

    int x = ve;
#pragma unroll
    for (int o = 1; o < 32; o <<= 1) {
        int y = __shfl_up_sync(0xffffffff, x, o);
        if (lane >= o) x += y;
    }
    if (lane == 31) wsum[wid] = x;
    __syncthreads();
    if (wid == 0) {
        int s = (lane < 16) ? wsum[lane] : 0;
#pragma unroll
        for (int o = 1; o < 16; o <<= 1) {
            int y = __shfl_up_sync(0xffffffff, s, o);
            if (lane >= o) s += y;
        }
        if (lane < 16) wsum[lane] = s;
    }
    __syncthreads();
    int incl = (wid ? wsum[wid - 1] : 0) + x;

    if (t == SCAN_B - 1) {
        unsigned long long pub = ((unsigned long long)incl << 2) | (b == 0 ? 2u : 1u);
        atomicExch(&g_scanstate[b], pub);
    }

    if (b > 0 && wid == 0) {
        long long run = 0;
        int j = b - 1;
        while (true) {
            int idx = j - lane;
            unsigned long long s;
            if (idx >= 0) {
                do { s = atomicAdd(&g_scanstate[idx], 0ull); } while ((s & 3) == 0);
            } else {
                s = 2ull;
            }
            unsigned mask = __ballot_sync(0xffffffff, (s & 3) == 2);
            long long contrib;
            if (mask) {
                int fl = __ffs(mask) - 1;
                contrib = (lane <= fl) ? (long long)(s >> 2) : 0;
            } else {
                contrib = (long long)(s >> 2);
            }
#pragma unroll
            for (int o = 16; o > 0; o >>= 1)
                contrib += __shfl_xor_sync(0xffffffff, contrib, o);
            run += contrib;
            if (mask) break;
            j -= 32;
        }
        if (lane == 0) s_prefix = (int)run;
    } else if (t == 0) {
        s_prefix = 0;
    }
    __syncthreads();
    int prefix = s_prefix;

    if (b > 0 && t == SCAN_B - 1)
        atomicExch(&g_scanstate[b], (((unsigned long long)(incl + prefix)) << 2) | 2u);

    if (i < N_NODES) {
        int o = prefix + incl - ve;      // exclusive scan of even-rounded degrees
        g_offcnt[i] = make_int2(o, v);   // (even base, TRUE degree)
        g_cur[i] = o;
    }
}

// 2 edges/thread: reads edge_index directly (no g_sd); CSR scatter.
// Also re-zeroes g_scanstate (k_scan is complete once this kernel starts).
__global__ void k_edge_fused(const void* __restrict__ ei) {
    if (blockIdx.x == 0 && threadIdx.x < SCAN_NB)
        g_scanstate[threadIdx.x] = 0ull;   // restore zero-init invariant
    int i = (blockIdx.x * blockDim.x + threadIdx.x) * 2;
    if (i >= N_EDGES) return;
    float M = g_maxs[0] + g_maxs[1];
    int s0, s1, d0, d1;
    if (g_flag) {
        const long long* p = (const long long*)ei;
        longlong2 a = __ldg((const longlong2*)(p + i));
        longlong2 c = __ldg((const longlong2*)(p + N_EDGES + i));
        s0 = (int)a.x; s1 = (int)a.y;
        d0 = (int)c.x; d1 = (int)c.y;
    } else {
        const int* p = (const int*)ei;
        int2 a = __ldg((const int2*)(p + i));
        int2 c = __ldg((const int2*)(p + N_EDGES + i));
        s0 = a.x; s1 = a.y;
        d0 = c.x; d1 = c.y;
    }
    float x0 = __ldg(&g_ssrc[s0]) + __ldg(&g_sdst[d0]);
    float x1 = __ldg(&g_ssrc[s1]) + __ldg(&g_sdst[d1]);
    float e0 = x0 > 0.f ? x0 : NEG_SLOPE * x0;
    float e1 = x1 > 0.f ? x1 : NEG_SLOPE * x1;
    float ex0 = __expf(e0 - M);
    float ex1 = __expf(e1 - M);
    int p0 = atomicAdd(&g_cur[d0], 1);
    g_edge[p0] = make_float2(ex0, __int_as_float(s0));
    int p1 = atomicAdd(&g_cur[d1], 1);
    g_edge[p1] = make_float2(ex1, __int_as_float(s1));
}

// warp per node; all 32 lanes own disjoint half2 columns, no cross-lane reduce.
// Bases are even -> all float4 edge loads aligned, no peel. (R9 loop shape.)
// Resets g_maxs to 0.0f = module-load state (valid shift: max(0, truemax)).
__global__ void k_aggregate(float* __restrict__ out) {
    if (blockIdx.x == 0 && threadIdx.x < 2)
        g_maxs[threadIdx.x] = 0.f;        // restore zero-init invariant
    int w    = (blockIdx.x * blockDim.x + threadIdx.x) >> 5;
    int lane = threadIdx.x & 31;
    if (w >= N_NODES) return;
    int2 oc = g_offcnt[w];               // one LDG.64: (even base, degree)
    int base = oc.x, deg = oc.y;
    const __half2* zrow = (const __half2*)g_zh;

    float ax = 0.f, ay = 0.f, wsum = 0.f;
    int j = 0;

    for (; j + 8 <= deg; j += 8) {
        const float4* ep = (const float4*)&g_edge[base + j];
        float4 ea = __ldg(ep);
        float4 eb = __ldg(ep + 1);
        float4 ec = __ldg(ep + 2);
        float4 ed = __ldg(ep + 3);
        __half2 z0 = __ldg(&zrow[__float_as_int(ea.y) * 32 + lane]);
        __half2 z1 = __ldg(&zrow[__float_as_int(ea.w) * 32 + lane]);
        __half2 z2 = __ldg(&zrow[__float_as_int(eb.y) * 32 + lane]);
        __half2 z3 = __ldg(&zrow[__float_as_int(eb.w) * 32 + lane]);
        __half2 z4 = __ldg(&zrow[__float_as_int(ec.y) * 32 + lane]);
        __half2 z5 = __ldg(&zrow[__float_as_int(ec.w) * 32 + lane]);
        __half2 z6 = __ldg(&zrow[__float_as_int(ed.y) * 32 + lane]);
        __half2 z7 = __ldg(&zrow[__float_as_int(ed.w) * 32 + lane]);
        float2 f;
        f = __half22float2(z0); ax += ea.x * f.x; ay += ea.x * f.y;
        f = __half22float2(z1); ax += ea.z * f.x; ay += ea.z * f.y;
        f = __half22float2(z2); ax += eb.x * f.x; ay += eb.x * f.y;
        f = __half22float2(z3); ax += eb.z * f.x; ay += eb.z * f.y;
        f = __half22float2(z4); ax += ec.x * f.x; ay += ec.x * f.y;
        f = __half22float2(z5); ax += ec.z * f.x; ay += ec.z * f.y;
        f = __half22float2(z6); ax += ed.x * f.x; ay += ed.x * f.y;
        f = __half22float2(z7); ax += ed.z * f.x; ay += ed.z * f.y;
        wsum += (ea.x + ea.z) + (eb.x + eb.z) + (ec.x + ec.z) + (ed.x + ed.z);
    }
    if (j + 4 <= deg) {
        const float4* ep = (const float4*)&g_edge[base + j];
        float4 ea = __ldg(ep);
        float4 eb = __ldg(ep + 1);
        __half2 z0 = __ldg(&zrow[__float_as_int(ea.y) * 32 + lane]);
        __half2 z1 = __ldg(&zrow[__float_as_int(ea.w) * 32 + lane]);
        __half2 z2 = __ldg(&zrow[__float_as_int(eb.y) * 32 + lane]);
        __half2 z3 = __ldg(&zrow[__float_as_int(eb.w) * 32 + lane]);
        float2 f;
        f = __half22float2(z0); ax += ea.x * f.x; ay += ea.x * f.y;
        f = __half22float2(z1); ax += ea.z * f.x; ay += ea.z * f.y;
        f = __half22float2(z2); ax += eb.x * f.x; ay += eb.x * f.y;
        f = __half22float2(z3); ax += eb.z * f.x; ay += eb.z * f.y;
        wsum += (ea.x + ea.z) + (eb.x + eb.z);
        j += 4;
    }
    for (; j < deg; j++) {
        float2 ed = __ldg((const float2*)&g_edge[base + j]);
        __half2 z = __ldg(&zrow[__float_as_int(ed.y) * 32 + lane]);
        float2 f = __half22float2(z);
        ax += ed.x * f.x; ay += ed.x * f.y; wsum += ed.x;
    }

    float inv = wsum > 0.f ? 1.f / wsum : 0.f;
    *(float2*)&out[w * OUT_DIM + lane * 2] = make_float2(ax * inv, ay * inv);
}

// ---------------- launch --------------------------------------------------------
extern "C" void kernel_launch(void* const* d_in, const int* in_sizes, int n_in,
                              void* d_out, int out_size) {
    const float* h = (const float*)d_in[0];
    const float* W = (const float*)d_in[1];
    const float* a = (const float*)d_in[2];
    const void*  ei = d_in[3];
    float* out = (float*)d_out;

    cudaFuncSetAttribute(k_fat, cudaFuncAttributeMaxDynamicSharedMemorySize, SMEM_TC_TOTAL);

    k_fat<<<NGB + NCB, 256, SMEM_TC_TOTAL>>>(h, W, a, ei);
    k_scan<<<SCAN_NB, SCAN_B>>>();
    k_edge_fused<<<(N_EDGES / 2 + 255) / 256, 256>>>(ei);
    k_aggregate<<<(N_NODES * 32 + 255) / 256, 256>>>(out);
}

// round 15
// speedup vs baseline: 1.2371x; 1.0023x over previous
#include <cuda_runtime.h>
#include <cuda_bf16.h>
#include <cuda_fp16.h>
#include <cstdint>

#define N_NODES 100000
#define N_EDGES 1600000
#define IN_DIM  256
#define OUT_DIM 64
#define NEG_SLOPE 0.01f

#define SCAN_B 512
#define SCAN_NB 196   // 196*512 = 100352 >= N_NODES

#define NGB 782                         // gemm blocks (ceil(100000/128))
#define NCB ((N_EDGES + 1023) / 1024)   // convert blocks, 4 edges/thread

// SMEM map for fat kernel: double-buffered bf16 hi/lo tiles (SW128 swizzle)
#define B_AHI 0
#define B_ALO 16384
#define B_BHI 32768
#define B_BLO 40960
#define BUF_SZ 49152
#define OFF_ATT 98304
#define OFF_SS0 98816
#define OFF_SS1 99328
#define SMEM_TC_TOTAL 99840   // 2 CTAs/SM

// ---------------- scratch (device globals; no allocations allowed) ----------
// Zero-init at module load; each launch restores that invariant (self-cleaning).
__device__ __half  g_zh[N_NODES * OUT_DIM];   // z in fp16 (L2-resident, 12.8MB)
__device__ float   g_ssrc[N_NODES];
__device__ float   g_sdst[N_NODES];
__device__ float2  g_edge[N_EDGES + N_NODES]; // (ex, src*32) CSR order, even bases
__device__ int     g_cnt[N_NODES];      // zero at entry; re-zeroed by k_scan
__device__ int2    g_offcnt[N_NODES];   // (even offset, degree): one LDG.64
__device__ int     g_cur[N_NODES];
__device__ float   g_maxs[2];           // 0.0 at entry; reset by k_aggregate
__device__ int     g_flag;              // edge_index dtype: 1 = int64, 0 = int32
__device__ unsigned long long g_scanstate[SCAN_NB];  // zeroed by k_edge_fused

// ---------------- helpers ------------------------------------------------------
__device__ __forceinline__ uint32_t smem_to_u32(const void* p) {
    uint32_t a;
    asm("{ .reg .u64 t; cvta.to.shared.u64 t, %1; cvt.u32.u64 %0, t; }"
        : "=r"(a) : "l"(p));
    return a;
}
__device__ __forceinline__ uint32_t swzoff(int row, int colb) {
    uint32_t b = (uint32_t)(row * 128 + colb);
    return b ^ ((b >> 3) & 0x70);
}
// packed f32x2 -> bf16x2: ONE cvt instruction (vs 2 cvt + 1 mov)
__device__ __forceinline__ uint32_t packf2(float a, float b) {
    __nv_bfloat162 t = __float22bfloat162_rn(make_float2(a, b));
    return *(uint32_t*)&t;
}
__device__ __forceinline__ float bf16lo_f(uint32_t v) { return __uint_as_float(v << 16); }
__device__ __forceinline__ float bf16hi_f(uint32_t v) { return __uint_as_float(v & 0xffff0000u); }

__device__ __forceinline__ void cvt_granule(const float4& p, const float4& q,
                                            uint4& hi, uint4& lo) {
    hi.x = packf2(p.x, p.y);
    hi.y = packf2(p.z, p.w);
    hi.z = packf2(q.x, q.y);
    hi.w = packf2(q.z, q.w);
    lo.x = packf2(p.x - bf16lo_f(hi.x), p.y - bf16hi_f(hi.x));
    lo.y = packf2(p.z - bf16lo_f(hi.y), p.w - bf16hi_f(hi.y));
    lo.z = packf2(q.x - bf16lo_f(hi.z), q.y - bf16hi_f(hi.z));
    lo.w = packf2(q.z - bf16lo_f(hi.w), q.w - bf16hi_f(hi.w));
}
__device__ __forceinline__ uint4 ldsm4(uint32_t addr) {
    uint4 r;
    asm volatile("ldmatrix.sync.aligned.m8n8.x4.shared.b16 {%0,%1,%2,%3}, [%4];"
        : "=r"(r.x), "=r"(r.y), "=r"(r.z), "=r"(r.w) : "r"(addr));
    return r;
}
__device__ __forceinline__ void mma_bf16(float* d, const uint4& A, uint32_t b0, uint32_t b1) {
    asm volatile("mma.sync.aligned.m16n8k16.row.col.f32.bf16.bf16.f32 "
        "{%0,%1,%2,%3}, {%4,%5,%6,%7}, {%8,%9}, {%0,%1,%2,%3};"
        : "+f"(d[0]), "+f"(d[1]), "+f"(d[2]), "+f"(d[3])
        : "r"(A.x), "r"(A.y), "r"(A.z), "r"(A.w), "r"(b0), "r"(b1));
}
__device__ __forceinline__ void atomicMaxFloat(float* addr, float v) {
    if (v >= 0.0f) atomicMax((int*)addr, __float_as_int(v));
    else           atomicMin((unsigned int*)addr, (unsigned int)__float_as_int(v));
}

// ---- GEMM building blocks ----
__device__ __forceinline__ void ldg_chunk(const float* __restrict__ h,
                                          const float* __restrict__ W,
                                          int r0, int k0, int tid,
                                          float4 fa[4][2], float4 fb[2][2]) {
#pragma unroll
    for (int j = 0; j < 4; j++) {
        int g = tid + j * 256;
        int row = g >> 3, c8 = g & 7;
        int gr = r0 + row;
        if (gr < N_NODES) {
            fa[j][0] = __ldg((const float4*)&h[gr * IN_DIM + k0 + c8 * 8]);
            fa[j][1] = __ldg((const float4*)&h[gr * IN_DIM + k0 + c8 * 8 + 4]);
        } else {
            fa[j][0] = make_float4(0.f, 0.f, 0.f, 0.f);
            fa[j][1] = make_float4(0.f, 0.f, 0.f, 0.f);
        }
    }
#pragma unroll
    for (int j = 0; j < 2; j++) {
        int g = tid + j * 256;
        int row = g >> 3, c8 = g & 7;
        fb[j][0] = __ldg((const float4*)&W[row * IN_DIM + k0 + c8 * 8]);
        fb[j][1] = __ldg((const float4*)&W[row * IN_DIM + k0 + c8 * 8 + 4]);
    }
}

__device__ __forceinline__ void cvt_sts(char* smem, int bufbase, int tid,
                                        const float4 fa[4][2], const float4 fb[2][2]) {
#pragma unroll
    for (int j = 0; j < 4; j++) {
        int g = tid + j * 256;
        int row = g >> 3, c8 = g & 7;
        uint4 hi, lo;
        cvt_granule(fa[j][0], fa[j][1], hi, lo);
        uint32_t off = swzoff(row, c8 * 16);
        *(uint4*)(smem + bufbase + B_AHI + off) = hi;
        *(uint4*)(smem + bufbase + B_ALO + off) = lo;
    }
#pragma unroll
    for (int j = 0; j < 2; j++) {
        int g = tid + j * 256;
        int row = g >> 3, c8 = g & 7;
        uint4 hi, lo;
        cvt_granule(fb[j][0], fb[j][1], hi, lo);
        uint32_t off = swzoff(row, c8 * 16);
        *(uint4*)(smem + bufbase + B_BHI + off) = hi;
        *(uint4*)(smem + bufbase + B_BLO + off) = lo;
    }
}

__device__ __forceinline__ void mma_chunk(uint32_t sbuf, int wr, int wc, int lane,
                                          float acc[2][4][4]) {
#pragma unroll
    for (int ks = 0; ks < 4; ks++) {
        uint4 Ah[2], Al[2], Bh[2], Bl[2];
        int arow  = wr * 32 + (lane & 15);
        int acolb = ks * 32 + ((lane >> 4) << 4);
#pragma unroll
        for (int mt = 0; mt < 2; mt++) {
            uint32_t ad = sbuf + B_AHI + swzoff(arow + mt * 16, acolb);
            Ah[mt] = ldsm4(ad);
            Al[mt] = ldsm4(ad + (B_ALO - B_AHI));
        }
        int brow  = wc * 32 + (lane & 7) + ((lane >> 4) << 3);
        int bcolb = ks * 32 + (((lane >> 3) & 1) << 4);
#pragma unroll
        for (int nb = 0; nb < 2; nb++) {
            uint32_t bd = sbuf + B_BHI + swzoff(brow + nb * 16, bcolb);
            Bh[nb] = ldsm4(bd);
            Bl[nb] = ldsm4(bd + (B_BLO - B_BHI));
        }
#pragma unroll
        for (int mt = 0; mt < 2; mt++)
#pragma unroll
            for (int nb = 0; nb < 2; nb++) {
                mma_bf16(acc[mt][nb * 2],     Ah[mt], Bh[nb].x, Bh[nb].y);
                mma_bf16(acc[mt][nb * 2 + 1], Ah[mt], Bh[nb].z, Bh[nb].w);
                mma_bf16(acc[mt][nb * 2],     Al[mt], Bh[nb].x, Bh[nb].y);
                mma_bf16(acc[mt][nb * 2 + 1], Al[mt], Bh[nb].z, Bh[nb].w);
                mma_bf16(acc[mt][nb * 2],     Ah[mt], Bl[nb].x, Bl[nb].y);
                mma_bf16(acc[mt][nb * 2 + 1], Ah[mt], Bl[nb].z, Bl[nb].w);
            }
    }
}

// ---------------- fat kernel: GEMM blocks [0, NGB) + convert blocks [NGB, ...) ---
__global__ __launch_bounds__(256, 2) void k_fat(const float* __restrict__ h,
                                                const float* __restrict__ W,
                                                const float* __restrict__ a_attn,
                                                const void* __restrict__ ei) {
    extern __shared__ char smem[];
    const int bid = blockIdx.x;
    const int tid = threadIdx.x;

    if (bid >= NGB) {
        // ---- convert path: count degrees only (edge_fused re-reads ei) ----
        __shared__ int s_flag;
        if (tid < 32) {
            const long long* p = (const long long*)ei;
            long long v = __ldg(&p[tid]);
            int ok = (v >= 0 && v < N_NODES);
            unsigned m = __ballot_sync(0xffffffff, ok);
            if (tid == 0) {
                s_flag = (m == 0xffffffffu);
                if (bid == NGB) g_flag = s_flag;   // publish dtype for edge_fused
            }
        }
        __syncthreads();
        int base = (bid - NGB) * 1024 + tid * 4;
        if (base + 3 >= N_EDGES) return;
        int d0, d1, d2, d3;
        if (s_flag) {
            const long long* p = (const long long*)ei;
            longlong2 c = __ldg((const longlong2*)(p + N_EDGES + base));
            longlong2 d = __ldg((const longlong2*)(p + N_EDGES + base + 2));
            d0 = (int)c.x; d1 = (int)c.y; d2 = (int)d.x; d3 = (int)d.y;
        } else {
            const int* p = (const int*)ei;
            int4 c = __ldg((const int4*)(p + N_EDGES + base));
            d0 = c.x; d1 = c.y; d2 = c.z; d3 = c.w;
        }
        atomicAdd(&g_cnt[d0], 1);
        atomicAdd(&g_cnt[d1], 1);
        atomicAdd(&g_cnt[d2], 1);
        atomicAdd(&g_cnt[d3], 1);
        return;
    }

    // ---------------- GEMM path ----------------
    const uint32_t sb = smem_to_u32(smem);
    const int lane = tid & 31, wid = tid >> 5;
    const int wr = wid & 3, wc = wid >> 2;
    const int r0 = bid * 128;

    float* sS0 = (float*)(smem + OFF_SS0);
    float* sS1 = (float*)(smem + OFF_SS1);
    if (tid < 128) {
        ((float*)(smem + OFF_ATT))[tid] = a_attn[tid];
        sS0[tid] = 0.f;
        sS1[tid] = 0.f;
    }

    float acc[2][4][4];
#pragma unroll
    for (int a = 0; a < 2; a++)
#pragma unroll
        for (int b = 0; b < 4; b++)
#pragma unroll
            for (int c = 0; c < 4; c++) acc[a][b][c] = 0.f;

    float4 fa[4][2], fb[2][2];
    ldg_chunk(h, W, r0, 0, tid, fa, fb);
    cvt_sts(smem, 0, tid, fa, fb);
    __syncthreads();

#pragma unroll
    for (int it = 1; it < 4; it++) {
        ldg_chunk(h, W, r0, it * 64, tid, fa, fb);
        mma_chunk(sb + ((it - 1) & 1) * BUF_SZ, wr, wc, lane, acc);
        cvt_sts(smem, (it & 1) * BUF_SZ, tid, fa, fb);
        __syncthreads();
    }
    mma_chunk(sb + BUF_SZ, wr, wc, lane, acc);

    const float* al = (const float*)(smem + OFF_ATT);
    const float* ar = al + OUT_DIM;
#pragma unroll
    for (int mt = 0; mt < 2; mt++) {
#pragma unroll
        for (int half = 0; half < 2; half++) {
            int lr = wr * 32 + mt * 16 + (lane >> 2) + half * 8;
            int grow = r0 + lr;
            float s0 = 0.f, s1 = 0.f;
#pragma unroll
            for (int nt = 0; nt < 4; nt++) {
                int c = wc * 32 + nt * 8 + (lane & 3) * 2;
                float v0 = acc[mt][nt][half * 2];
                float v1 = acc[mt][nt][half * 2 + 1];
                s0 += v0 * al[c] + v1 * al[c + 1];
                s1 += v0 * ar[c] + v1 * ar[c + 1];
                if (grow < N_NODES)
                    *(__half2*)&g_zh[grow * OUT_DIM + c] = __floats2half2_rn(v0, v1);
            }
            s0 += __shfl_xor_sync(0xffffffff, s0, 1);
            s0 += __shfl_xor_sync(0xffffffff, s0, 2);
            s1 += __shfl_xor_sync(0xffffffff, s1, 1);
            s1 += __shfl_xor_sync(0xffffffff, s1, 2);
            if ((lane & 3) == 0) {
                atomicAdd(&sS0[lr], s0);
                atomicAdd(&sS1[lr], s1);
            }
        }
    }
    __syncthreads();
    if (tid < 128) {
        int grow = r0 + tid;
        float s0 = sS0[tid], s1 = sS1[tid];
        if (grow < N_NODES) {
            g_ssrc[grow] = s0;
            g_sdst[grow] = s1;
        } else {
            s0 = __int_as_float(0xff800000);
            s1 = __int_as_float(0xff800000);
        }
#pragma unroll
        for (int o = 16; o > 0; o >>= 1) {
            s0 = fmaxf(s0, __shfl_xor_sync(0xffffffff, s0, o));
            s1 = fmaxf(s1, __shfl_xor_sync(0xffffffff, s1, o));
        }
        if ((tid & 31) == 0) {
            atomicMaxFloat(&g_maxs[0], s0);
            atomicMaxFloat(&g_maxs[1], s1);
        }
    }
}

// ---------------- single-pass scan with decoupled lookback ----------------------
// Scans even-rounded degrees (deg + (deg&1)) so every CSR base is 16B-aligned.
// Also re-zeroes g_cnt for the next launch.
__global__ void k_scan() {
    __shared__ int wsum[16];
    __shared__ int s_prefix;
    const int b = blockIdx.x, t = threadIdx.x;
    const int lane = t & 31, wid = t >> 5;
    const int i = b * SCAN_B + t;
    int v = (i < N_NODES) ? g_cnt[i] : 0;
    if (i < N_NODES) g_cnt[i] = 0;       // restore zero-init invariant
    int ve = v + (v & 1);                // even-rounded for aligned bases

    int x = ve;
#pragma unroll
    for (int o = 1; o < 32; o <<= 1) {
        int y = __shfl_up_sync(0xffffffff, x, o);
        if (lane >= o) x += y;
    }
    if (lane == 31) wsum[wid] = x;
    __syncthreads();
    if (wid == 0) {
        int s = (lane < 16) ? wsum[lane] : 0;
#pragma unroll
        for (int o = 1; o < 16; o <<= 1) {
            int y = __shfl_up_sync(0xffffffff, s, o);
            if (lane >= o) s += y;
        }
        if (lane < 16) wsum[lane] = s;
    }
    __syncthreads();
    int incl = (wid ? wsum[wid - 1] : 0) + x;

    if (t == SCAN_B - 1) {
        unsigned long long pub = ((unsigned long long)incl << 2) | (b == 0 ? 2u : 1u);
        atomicExch(&g_scanstate[b], pub);
    }

    if (b > 0 && wid == 0) {
        long long run = 0;
        int j = b - 1;
        while (true) {
            int idx = j - lane;
            unsigned long long s;
            if (idx >= 0) {
                do { s = atomicAdd(&g_scanstate[idx], 0ull); } while ((s & 3) == 0);
            } else {
                s = 2ull;
            }
            unsigned mask = __ballot_sync(0xffffffff, (s & 3) == 2);
            long long contrib;
            if (mask) {
                int fl = __ffs(mask) - 1;
                contrib = (lane <= fl) ? (long long)(s >> 2) : 0;
            } else {
                contrib = (long long)(s >> 2);
            }
#pragma unroll
            for (int o = 16; o > 0; o >>= 1)
                contrib += __shfl_xor_sync(0xffffffff, contrib, o);
            run += contrib;
            if (mask) break;
            j -= 32;
        }
        if (lane == 0) s_prefix = (int)run;
    } else if (t == 0) {
        s_prefix = 0;
    }
    __syncthreads();
    int prefix = s_prefix;

    if (b > 0 && t == SCAN_B - 1)
        atomicExch(&g_scanstate[b], (((unsigned long long)(incl + prefix)) << 2) | 2u);

    if (i < N_NODES) {
        int o = prefix + incl - ve;      // exclusive scan of even-rounded degrees
        g_offcnt[i] = make_int2(o, v);   // (even base, TRUE degree)
        g_cur[i] = o;
    }
}

// 2 edges/thread: reads edge_index directly; stores src premultiplied by 32
// (half2 row index) so the aggregate does IADD not IMAD per z-load.
// Also re-zeroes g_scanstate.
__global__ void k_edge_fused(const void* __restrict__ ei) {
    if (blockIdx.x == 0 && threadIdx.x < SCAN_NB)
        g_scanstate[threadIdx.x] = 0ull;   // restore zero-init invariant
    int i = (blockIdx.x * blockDim.x + threadIdx.x) * 2;
    if (i >= N_EDGES) return;
    float M = g_maxs[0] + g_maxs[1];
    int s0, s1, d0, d1;
    if (g_flag) {
        const long long* p = (const long long*)ei;
        longlong2 a = __ldg((const longlong2*)(p + i));
        longlong2 c = __ldg((const longlong2*)(p + N_EDGES + i));
        s0 = (int)a.x; s1 = (int)a.y;
        d0 = (int)c.x; d1 = (int)c.y;
    } else {
        const int* p = (const int*)ei;
        int2 a = __ldg((const int2*)(p + i));
        int2 c = __ldg((const int2*)(p + N_EDGES + i));
        s0 = a.x; s1 = a.y;
        d0 = c.x; d1 = c.y;
    }
    float x0 = __ldg(&g_ssrc[s0]) + __ldg(&g_sdst[d0]);
    float x1 = __ldg(&g_ssrc[s1]) + __ldg(&g_sdst[d1]);
    float e0 = x0 > 0.f ? x0 : NEG_SLOPE * x0;
    float e1 = x1 > 0.f ? x1 : NEG_SLOPE * x1;
    float ex0 = __expf(e0 - M);
    float ex1 = __expf(e1 - M);
    int p0 = atomicAdd(&g_cur[d0], 1);
    g_edge[p0] = make_float2(ex0, __int_as_float(s0 * 32));
    int p1 = atomicAdd(&g_cur[d1], 1);
    g_edge[p1] = make_float2(ex1, __int_as_float(s1 * 32));
}

// warp per node; all 32 lanes own disjoint half2 columns, no cross-lane reduce.
// src field is pre-scaled (x32): z index = srcpre + lane (IADD only).
// Resets g_maxs to 0.0f = module-load state (valid shift: max(0, truemax)).
__global__ void k_aggregate(float* __restrict__ out) {
    if (blockIdx.x == 0 && threadIdx.x < 2)
        g_maxs[threadIdx.x] = 0.f;        // restore zero-init invariant
    int w    = (blockIdx.x * blockDim.x + threadIdx.x) >> 5;
    int lane = threadIdx.x & 31;
    if (w >= N_NODES) return;
    int2 oc = g_offcnt[w];               // one LDG.64: (even base, degree)
    int base = oc.x, deg = oc.y;
    const __half2* zrow = (const __half2*)g_zh;

    float ax = 0.f, ay = 0.f, wsum = 0.f;
    int j = 0;

    for (; j + 8 <= deg; j += 8) {
        const float4* ep = (const float4*)&g_edge[base + j];
        float4 ea = __ldg(ep);
        float4 eb = __ldg(ep + 1);
        float4 ec = __ldg(ep + 2);
        float4 ed = __ldg(ep + 3);
        __half2 z0 = __ldg(&zrow[__float_as_int(ea.y) + lane]);
        __half2 z1 = __ldg(&zrow[__float_as_int(ea.w) + lane]);
        __half2 z2 = __ldg(&zrow[__float_as_int(eb.y) + lane]);
        __half2 z3 = __ldg(&zrow[__float_as_int(eb.w) + lane]);
        __half2 z4 = __ldg(&zrow[__float_as_int(ec.y) + lane]);
        __half2 z5 = __ldg(&zrow[__float_as_int(ec.w) + lane]);
        __half2 z6 = __ldg(&zrow[__float_as_int(ed.y) + lane]);
        __half2 z7 = __ldg(&zrow[__float_as_int(ed.w) + lane]);
        float2 f;
        f = __half22float2(z0); ax += ea.x * f.x; ay += ea.x * f.y;
        f = __half22float2(z1); ax += ea.z * f.x; ay += ea.z * f.y;
        f = __half22float2(z2); ax += eb.x * f.x; ay += eb.x * f.y;
        f = __half22float2(z3); ax += eb.z * f.x; ay += eb.z * f.y;
        f = __half22float2(z4); ax += ec.x * f.x; ay += ec.x * f.y;
        f = __half22float2(z5); ax += ec.z * f.x; ay += ec.z * f.y;
        f = __half22float2(z6); ax += ed.x * f.x; ay += ed.x * f.y;
        f = __half22float2(z7); ax += ed.z * f.x; ay += ed.z * f.y;
        wsum += (ea.x + ea.z) + (eb.x + eb.z) + (ec.x + ec.z) + (ed.x + ed.z);
    }
    if (j + 4 <= deg) {
        const float4* ep = (const float4*)&g_edge[base + j];
        float4 ea = __ldg(ep);
        float4 eb = __ldg(ep + 1);
        __half2 z0 = __ldg(&zrow[__float_as_int(ea.y) + lane]);
        __half2 z1 = __ldg(&zrow[__float_as_int(ea.w) + lane]);
        __half2 z2 = __ldg(&zrow[__float_as_int(eb.y) + lane]);
        __half2 z3 = __ldg(&zrow[__float_as_int(eb.w) + lane]);
        float2 f;
        f = __half22float2(z0); ax += ea.x * f.x; ay += ea.x * f.y;
        f = __half22float2(z1); ax += ea.z * f.x; ay += ea.z * f.y;
        f = __half22float2(z2); ax += eb.x * f.x; ay += eb.x * f.y;
        f = __half22float2(z3); ax += eb.z * f.x; ay += eb.z * f.y;
        wsum += (ea.x + ea.z) + (eb.x + eb.z);
        j += 4;
    }
    for (; j < deg; j++) {
        float2 ed = __ldg((const float2*)&g_edge[base + j]);
        __half2 z = __ldg(&zrow[__float_as_int(ed.y) + lane]);
        float2 f = __half22float2(z);
        ax += ed.x * f.x; ay += ed.x * f.y; wsum += ed.x;
    }

    float inv = wsum > 0.f ? 1.f / wsum : 0.f;
    *(float2*)&out[w * OUT_DIM + lane * 2] = make_float2(ax * inv, ay * inv);
}

// ---------------- launch --------------------------------------------------------
extern "C" void kernel_launch(void* const* d_in, const int* in_sizes, int n_in,
                              void* d_out, int out_size) {
    const float* h = (const float*)d_in[0];
    const float* W = (const float*)d_in[1];
    const float* a = (const float*)d_in[2];
    const void*  ei = d_in[3];
    float* out = (float*)d_out;

    cudaFuncSetAttribute(k_fat, cudaFuncAttributeMaxDynamicSharedMemorySize, SMEM_TC_TOTAL);

    k_fat<<<NGB + NCB, 256, SMEM_TC_TOTAL>>>(h, W, a, ei);
    k_scan<<<SCAN_NB, SCAN_B>>>();
    k_edge_fused<<<(N_EDGES / 2 + 255) / 256, 256>>>(ei);
    k_aggregate<<<(N_NODES * 32 + 255) / 256, 256>>>(out);
}